// round 2
// baseline (speedup 1.0000x reference)
#include <cuda_runtime.h>
#include <math.h>

#define SQ 2048           // sequence length
#define NH 16             // attention heads
#define DNN 128           // nope dim
#define DRR 64            // rope dim
#define DVV 128           // v dim
#define QRR 1536
#define KRR 512
#define HII 32            // indexer heads
#define DII 128           // indexer dim
#define TOPK 512
#define DMM 2048

// ---------------- scratch (device globals; no allocation allowed) ----------
__device__ float g_qr   [SQ * QRR];
__device__ float g_q    [SQ * NH * (DNN+DRR)]; // [s,16,192]
__device__ float g_kvall[SQ * (KRR + DRR)];    // [s,576]
__device__ float g_kv   [SQ * KRR];
__device__ float g_kvp  [SQ * NH * (DNN+DVV)]; // [s,16,256]
__device__ float g_k    [SQ * NH * (DNN+DRR)]; // [s,16,192]
__device__ float g_qi   [SQ * HII * DII];      // [s,32,128]
__device__ float g_ki   [SQ * DII];
__device__ float g_wts  [SQ * HII];
__device__ float g_iscore[SQ * SQ];
__device__ float g_comb [SQ * SQ];
__device__ float g_scores[67108864];           // [16, s, t]
__device__ float g_attnout[SQ * DMM];

#define NEG_INF (__int_as_float(0xff800000))

// ===================== 128x128x16 double-buffered NT GEMM ==================
// C = alpha * A @ B^T. A: MxK (lda), B: NxK (ldb), C: MxN (ldc). batch via z.
__global__ __launch_bounds__(256) void gemm_nt_k(
    const float* __restrict__ A, long sa, int lda,
    const float* __restrict__ B, long sb, int ldb,
    float* __restrict__ C, long sc, int ldc,
    int M, int N, int K, float alpha, int causal)
{
    A += (long)blockIdx.z * sa; B += (long)blockIdx.z * sb; C += (long)blockIdx.z * sc;
    int n0 = blockIdx.x * 128, m0 = blockIdx.y * 128;
    if (causal && n0 > m0 + 127) return;

    __shared__ float As[2][16][128];
    __shared__ float Bs[2][16][128];

    int tx = threadIdx.x, ty = threadIdx.y;
    int tid = ty * 16 + tx;
    int lrow = tid >> 1;            // 0..127
    int lcol = (tid & 1) * 8;       // 0 or 8

    const float* Ap = A + (long)(m0 + lrow) * lda + lcol;
    const float* Bp = B + (long)(n0 + lrow) * ldb + lcol;
    bool aval = (m0 + lrow) < M;
    bool bval = (n0 + lrow) < N;

    float4 ra0, ra1, rb0, rb1;
    const float4 z4 = make_float4(0.f, 0.f, 0.f, 0.f);

    // prologue: load k-tile 0
    ra0 = aval ? *(const float4*)(Ap)     : z4;
    ra1 = aval ? *(const float4*)(Ap + 4) : z4;
    rb0 = bval ? *(const float4*)(Bp)     : z4;
    rb1 = bval ? *(const float4*)(Bp + 4) : z4;
    As[0][lcol+0][lrow]=ra0.x; As[0][lcol+1][lrow]=ra0.y; As[0][lcol+2][lrow]=ra0.z; As[0][lcol+3][lrow]=ra0.w;
    As[0][lcol+4][lrow]=ra1.x; As[0][lcol+5][lrow]=ra1.y; As[0][lcol+6][lrow]=ra1.z; As[0][lcol+7][lrow]=ra1.w;
    Bs[0][lcol+0][lrow]=rb0.x; Bs[0][lcol+1][lrow]=rb0.y; Bs[0][lcol+2][lrow]=rb0.z; Bs[0][lcol+3][lrow]=rb0.w;
    Bs[0][lcol+4][lrow]=rb1.x; Bs[0][lcol+5][lrow]=rb1.y; Bs[0][lcol+6][lrow]=rb1.z; Bs[0][lcol+7][lrow]=rb1.w;
    __syncthreads();

    float acc[8][8] = {};
    int nk = K >> 4;
    for (int kt = 0; kt < nk; kt++) {
        int cur = kt & 1;
        if (kt + 1 < nk) {
            const float* Ap2 = Ap + (kt + 1) * 16;
            const float* Bp2 = Bp + (kt + 1) * 16;
            ra0 = aval ? *(const float4*)(Ap2)     : z4;
            ra1 = aval ? *(const float4*)(Ap2 + 4) : z4;
            rb0 = bval ? *(const float4*)(Bp2)     : z4;
            rb1 = bval ? *(const float4*)(Bp2 + 4) : z4;
        }
        #pragma unroll
        for (int k = 0; k < 16; k++) {
            float4 a0 = *(const float4*)(&As[cur][k][ty * 8]);
            float4 a1 = *(const float4*)(&As[cur][k][ty * 8 + 4]);
            float4 b0 = *(const float4*)(&Bs[cur][k][tx * 8]);
            float4 b1 = *(const float4*)(&Bs[cur][k][tx * 8 + 4]);
            float a[8] = {a0.x,a0.y,a0.z,a0.w,a1.x,a1.y,a1.z,a1.w};
            float b[8] = {b0.x,b0.y,b0.z,b0.w,b1.x,b1.y,b1.z,b1.w};
            #pragma unroll
            for (int i = 0; i < 8; i++)
                #pragma unroll
                for (int j = 0; j < 8; j++)
                    acc[i][j] += a[i] * b[j];
        }
        if (kt + 1 < nk) {
            int nx = cur ^ 1;
            As[nx][lcol+0][lrow]=ra0.x; As[nx][lcol+1][lrow]=ra0.y; As[nx][lcol+2][lrow]=ra0.z; As[nx][lcol+3][lrow]=ra0.w;
            As[nx][lcol+4][lrow]=ra1.x; As[nx][lcol+5][lrow]=ra1.y; As[nx][lcol+6][lrow]=ra1.z; As[nx][lcol+7][lrow]=ra1.w;
            Bs[nx][lcol+0][lrow]=rb0.x; Bs[nx][lcol+1][lrow]=rb0.y; Bs[nx][lcol+2][lrow]=rb0.z; Bs[nx][lcol+3][lrow]=rb0.w;
            Bs[nx][lcol+4][lrow]=rb1.x; Bs[nx][lcol+5][lrow]=rb1.y; Bs[nx][lcol+6][lrow]=rb1.z; Bs[nx][lcol+7][lrow]=rb1.w;
        }
        __syncthreads();
    }

    #pragma unroll
    for (int i = 0; i < 8; i++) {
        int m = m0 + ty * 8 + i;
        if (m >= M) continue;
        int n = n0 + tx * 8;
        if (n < N) {
            float4 o0 = make_float4(acc[i][0]*alpha, acc[i][1]*alpha, acc[i][2]*alpha, acc[i][3]*alpha);
            float4 o1 = make_float4(acc[i][4]*alpha, acc[i][5]*alpha, acc[i][6]*alpha, acc[i][7]*alpha);
            *(float4*)(C + (long)m * ldc + n)     = o0;
            *(float4*)(C + (long)m * ldc + n + 4) = o1;
        }
    }
}

// ===================== PV GEMM: out[.,h,:] = probs_h @ v_h (NN) ============
__global__ __launch_bounds__(256) void pv_gemm_k(
    const float* __restrict__ probs, const float* __restrict__ kvp,
    float* __restrict__ out)
{
    int h = blockIdx.z;
    const float* A = probs + (long)h * SQ * SQ;     // [m][k], lda=SQ
    const float* B = kvp + h * 256 + 128;           // [k][n], ldb=4096
    float* C = out + h * 128;                       // ldc=2048
    int m0 = blockIdx.y * 128;                      // n0 = 0 (N=128)
    int Kmax = m0 + 128;                            // probs zero beyond diag

    __shared__ float As[2][16][128];
    __shared__ float Bs[2][16][128];

    int tx = threadIdx.x, ty = threadIdx.y;
    int tid = ty * 16 + tx;
    int arow = tid >> 1, acol = (tid & 1) * 8;      // A: 128 m x 16 k
    int brow = tid >> 4, bcol = (tid & 15) * 8;     // B: 16 k x 128 n

    const float* Ap = A + (long)(m0 + arow) * SQ + acol;
    const float* Bp = B + (long)brow * 4096 + bcol;

    float4 ra0, ra1, rb0, rb1;
    ra0 = *(const float4*)(Ap);
    ra1 = *(const float4*)(Ap + 4);
    rb0 = *(const float4*)(Bp);
    rb1 = *(const float4*)(Bp + 4);
    As[0][acol+0][arow]=ra0.x; As[0][acol+1][arow]=ra0.y; As[0][acol+2][arow]=ra0.z; As[0][acol+3][arow]=ra0.w;
    As[0][acol+4][arow]=ra1.x; As[0][acol+5][arow]=ra1.y; As[0][acol+6][arow]=ra1.z; As[0][acol+7][arow]=ra1.w;
    *(float4*)(&Bs[0][brow][bcol])   = rb0;
    *(float4*)(&Bs[0][brow][bcol+4]) = rb1;
    __syncthreads();

    float acc[8][8] = {};
    int nk = Kmax >> 4;
    for (int kt = 0; kt < nk; kt++) {
        int cur = kt & 1;
        if (kt + 1 < nk) {
            const float* Ap2 = Ap + (kt + 1) * 16;
            const float* Bp2 = Bp + (long)(kt + 1) * 16 * 4096;
            ra0 = *(const float4*)(Ap2);
            ra1 = *(const float4*)(Ap2 + 4);
            rb0 = *(const float4*)(Bp2);
            rb1 = *(const float4*)(Bp2 + 4);
        }
        #pragma unroll
        for (int k = 0; k < 16; k++) {
            float4 a0 = *(const float4*)(&As[cur][k][ty * 8]);
            float4 a1 = *(const float4*)(&As[cur][k][ty * 8 + 4]);
            float4 b0 = *(const float4*)(&Bs[cur][k][tx * 8]);
            float4 b1 = *(const float4*)(&Bs[cur][k][tx * 8 + 4]);
            float a[8] = {a0.x,a0.y,a0.z,a0.w,a1.x,a1.y,a1.z,a1.w};
            float b[8] = {b0.x,b0.y,b0.z,b0.w,b1.x,b1.y,b1.z,b1.w};
            #pragma unroll
            for (int i = 0; i < 8; i++)
                #pragma unroll
                for (int j = 0; j < 8; j++)
                    acc[i][j] += a[i] * b[j];
        }
        if (kt + 1 < nk) {
            int nx = cur ^ 1;
            As[nx][acol+0][arow]=ra0.x; As[nx][acol+1][arow]=ra0.y; As[nx][acol+2][arow]=ra0.z; As[nx][acol+3][arow]=ra0.w;
            As[nx][acol+4][arow]=ra1.x; As[nx][acol+5][arow]=ra1.y; As[nx][acol+6][arow]=ra1.z; As[nx][acol+7][arow]=ra1.w;
            *(float4*)(&Bs[nx][brow][bcol])   = rb0;
            *(float4*)(&Bs[nx][brow][bcol+4]) = rb1;
        }
        __syncthreads();
    }

    #pragma unroll
    for (int i = 0; i < 8; i++) {
        int m = m0 + ty * 8 + i;
        float4 o0 = make_float4(acc[i][0], acc[i][1], acc[i][2], acc[i][3]);
        float4 o1 = make_float4(acc[i][4], acc[i][5], acc[i][6], acc[i][7]);
        *(float4*)(C + (long)m * 2048 + tx * 8)     = o0;
        *(float4*)(C + (long)m * 2048 + tx * 8 + 4) = o1;
    }
}

// ---------------- rmsnorm (per row) ----------------------------------------
__global__ void rmsnorm_k(const float* __restrict__ in, int ldi,
                          float* __restrict__ out, int ldo,
                          const float* __restrict__ w, int D)
{
    int s = blockIdx.x, tid = threadIdx.x;
    __shared__ float red[256];
    const float* ip = in + (long)s * ldi;
    float ss = 0.f;
    for (int d = tid; d < D; d += 256) { float v = ip[d]; ss += v * v; }
    red[tid] = ss; __syncthreads();
    for (int o = 128; o > 0; o >>= 1) { if (tid < o) red[tid] += red[tid + o]; __syncthreads(); }
    float scale = rsqrtf(red[0] / (float)D + 1e-6f);
    float* op = out + (long)s * ldo;
    for (int d = tid; d < D; d += 256) op[d] = ip[d] * scale * w[d];
}

// ---------------- rope (interleaved) on q's last 64 dims, in-place --------
__global__ void rope_q_k(float* __restrict__ q,
                         const float* __restrict__ cs, const float* __restrict__ sn)
{
    int s = blockIdx.x;
    int tid = threadIdx.x;       // 512 = 16 heads * 32 pairs
    int h = tid >> 5, i = tid & 31;
    float c = cs[s * 32 + i], si = sn[s * 32 + i];
    float* p = q + (long)s * 3072 + h * 192 + 128 + 2 * i;
    float x0 = p[0], x1 = p[1];
    p[0] = x0 * c - x1 * si;
    p[1] = x0 * si + x1 * c;
}

// ---------------- assemble k = [kvp[...,:128], rope(k_pe)] -----------------
__global__ void build_k_k(const float* __restrict__ kvp, const float* __restrict__ kvall,
                          float* __restrict__ kk,
                          const float* __restrict__ cs, const float* __restrict__ sn)
{
    int s = blockIdx.x, h = blockIdx.y;
    int tid = threadIdx.x;       // 128
    float* dst = kk + ((long)s * 16 + h) * 192;
    dst[tid] = kvp[(long)s * 4096 + h * 256 + tid];
    if (tid < 32) {
        float c = cs[s * 32 + tid], si = sn[s * 32 + tid];
        float x0 = kvall[(long)s * 576 + 512 + 2 * tid];
        float x1 = kvall[(long)s * 576 + 513 + 2 * tid];
        dst[128 + 2 * tid] = x0 * c - x1 * si;
        dst[129 + 2 * tid] = x0 * si + x1 * c;
    }
}

// ---------------- rope_half on qi first 64 dims per head, in-place --------
__global__ void rope_qi_k(float* __restrict__ qi,
                          const float* __restrict__ cs, const float* __restrict__ sn)
{
    int s = blockIdx.x;
    int tid = threadIdx.x;       // 1024 = 32 heads * 32 dims
    int h = tid >> 5, d = tid & 31;
    float c = cs[s * 32 + d], si = sn[s * 32 + d];
    float* p = qi + (long)s * 4096 + h * 128;
    float x0 = p[d], x1 = p[d + 32];
    p[d] = x0 * c - x1 * si;
    p[d + 32] = x0 * si + x1 * c;
}

// ---------------- layernorm + rope_half for ki (in-place, width 128) ------
__global__ void ln_rope_ki_k(float* __restrict__ ki,
                             const float* __restrict__ w, const float* __restrict__ b,
                             const float* __restrict__ cs, const float* __restrict__ sn)
{
    int s = blockIdx.x, tid = threadIdx.x;   // 128
    __shared__ float red[128];
    __shared__ float buf[128];
    float v = ki[(long)s * 128 + tid];
    red[tid] = v; __syncthreads();
    for (int o = 64; o > 0; o >>= 1) { if (tid < o) red[tid] += red[tid + o]; __syncthreads(); }
    float mean = red[0] / 128.f; __syncthreads();
    float d = v - mean;
    red[tid] = d * d; __syncthreads();
    for (int o = 64; o > 0; o >>= 1) { if (tid < o) red[tid] += red[tid + o]; __syncthreads(); }
    float var = red[0] / 128.f;
    float nv = d * rsqrtf(var + 1e-5f) * w[tid] + b[tid];
    buf[tid] = nv; __syncthreads();
    float out;
    if (tid < 32) {
        float c = cs[s * 32 + tid], si = sn[s * 32 + tid];
        out = buf[tid] * c - buf[tid + 32] * si;
    } else if (tid < 64) {
        int i = tid - 32;
        float c = cs[s * 32 + i], si = sn[s * 32 + i];
        out = buf[i] * si + buf[i + 32] * c;
    } else {
        out = nv;
    }
    ki[(long)s * 128 + tid] = out;
}

// =============== indexer: sum_h relu(qi_h . ki / sqrt(128)) * w ============
// tile: 128 s-rows x 64 t-cols; ki tile resident in smem across 32 heads.
__global__ __launch_bounds__(256) void indexer_k(
    const float* __restrict__ qi, const float* __restrict__ ki,
    const float* __restrict__ wts, float* __restrict__ out)
{
    int t0 = blockIdx.x * 64, s0 = blockIdx.y * 128;
    if (t0 > s0 + 127) return;

    __shared__ float Bs[128][64];   // ki [k][t]  32KB
    __shared__ float As[16][128];   // qi chunk [k][s]  8KB
    __shared__ float Ws[128][16];   // wts group [s][h] 8KB

    int tx = threadIdx.x, ty = threadIdx.y;
    int tid = ty * 16 + tx;

    // load ki tile (transposed)
    {
        int t = tid >> 2, kb = (tid & 3) * 32;
        const float* kp = ki + (long)(t0 + t) * 128 + kb;
        #pragma unroll
        for (int c = 0; c < 32; c += 4) {
            float4 v = *(const float4*)(kp + c);
            Bs[kb+c][t] = v.x; Bs[kb+c+1][t] = v.y; Bs[kb+c+2][t] = v.z; Bs[kb+c+3][t] = v.w;
        }
    }

    const float scl = 0.08838834764831845f;  // 1/sqrt(128)
    float fin[8][4] = {};
    int arow = tid >> 1, acol = (tid & 1) * 8;

    for (int hg = 0; hg < 2; hg++) {
        __syncthreads();   // Bs ready (first iter) / Ws reuse safe
        for (int i = tid; i < 2048; i += 256)
            Ws[i >> 4][i & 15] = wts[(long)(s0 + (i >> 4)) * 32 + hg * 16 + (i & 15)];
        __syncthreads();

        for (int hh = 0; hh < 16; hh++) {
            int h = hg * 16 + hh;
            float acc[8][4] = {};
            #pragma unroll
            for (int kc = 0; kc < 8; kc++) {
                const float* qp = qi + (long)(s0 + arow) * 4096 + h * 128 + kc * 16 + acol;
                float4 v0 = *(const float4*)(qp);
                float4 v1 = *(const float4*)(qp + 4);
                __syncthreads();   // previous chunk consumed
                As[acol+0][arow]=v0.x; As[acol+1][arow]=v0.y; As[acol+2][arow]=v0.z; As[acol+3][arow]=v0.w;
                As[acol+4][arow]=v1.x; As[acol+5][arow]=v1.y; As[acol+6][arow]=v1.z; As[acol+7][arow]=v1.w;
                __syncthreads();
                #pragma unroll
                for (int k = 0; k < 16; k++) {
                    float4 a0 = *(const float4*)(&As[k][ty * 8]);
                    float4 a1 = *(const float4*)(&As[k][ty * 8 + 4]);
                    float4 b4 = *(const float4*)(&Bs[kc * 16 + k][tx * 4]);
                    float a[8] = {a0.x,a0.y,a0.z,a0.w,a1.x,a1.y,a1.z,a1.w};
                    float b[4] = {b4.x,b4.y,b4.z,b4.w};
                    #pragma unroll
                    for (int i = 0; i < 8; i++)
                        #pragma unroll
                        for (int j = 0; j < 4; j++)
                            acc[i][j] += a[i] * b[j];
                }
            }
            #pragma unroll
            for (int i = 0; i < 8; i++) {
                float wv = Ws[ty * 8 + i][hh];
                #pragma unroll
                for (int j = 0; j < 4; j++)
                    fin[i][j] += fmaxf(acc[i][j] * scl, 0.f) * wv;
            }
        }
    }

    #pragma unroll
    for (int i = 0; i < 8; i++) {
        float4 o = make_float4(fin[i][0], fin[i][1], fin[i][2], fin[i][3]);
        *(float4*)(out + (long)(s0 + ty * 8 + i) * SQ + t0 + tx * 4) = o;
    }
}

// ---------------- per-row top-512 -> combined mask (0 keep / -inf drop) ---
__global__ __launch_bounds__(1024) void topk_mask_k(
    const float* __restrict__ iscore, float* __restrict__ comb)
{
    int s = blockIdx.x, tid = threadIdx.x;
    __shared__ float sv[2048];
    __shared__ float xo[2048];
    __shared__ unsigned char sel[2048];
    __shared__ int s_cnt;
    for (int t = tid; t < 2048; t += 1024) {
        float v = (t <= s) ? iscore[(long)s * SQ + t] : NEG_INF;
        xo[t] = v; sv[t] = v; sel[t] = 0;
    }
    if (tid == 0) s_cnt = 0;
    __syncthreads();

    if (s <= TOPK - 1) {  // <=512 causal entries: keep all
        for (int t = tid; t < 2048; t += 1024)
            comb[(long)s * SQ + t] = (t <= s) ? 0.f : NEG_INF;
        return;
    }
    // bitonic sort ascending
    for (int k = 2; k <= 2048; k <<= 1) {
        for (int j = k >> 1; j > 0; j >>= 1) {
            for (int t = tid; t < 2048; t += 1024) {
                int ixj = t ^ j;
                if (ixj > t) {
                    float a = sv[t], b = sv[ixj];
                    bool asc = ((t & k) == 0);
                    if (asc ? (a > b) : (a < b)) { sv[t] = b; sv[ixj] = a; }
                }
            }
            __syncthreads();
        }
    }
    float T = sv[2048 - TOPK];   // 512th largest
    int local = 0;
    for (int t = tid; t <= s; t += 1024)
        if (xo[t] > T) { sel[t] = 1; local++; }
    atomicAdd(&s_cnt, local);
    __syncthreads();
    if (tid == 0) {
        int quota = TOPK - s_cnt;    // ties at T by lowest index (jax tie-break)
        for (int t = 0; t <= s && quota > 0; t++)
            if (!sel[t] && xo[t] == T) { sel[t] = 1; quota--; }
    }
    __syncthreads();
    for (int t = tid; t < 2048; t += 1024)
        comb[(long)s * SQ + t] = sel[t] ? 0.f : NEG_INF;
}

// ---------------- masked softmax over t, in-place on g_scores --------------
__global__ void softmax_k(float* __restrict__ scores, const float* __restrict__ comb)
{
    int s = blockIdx.x, h = blockIdx.y, tid = threadIdx.x;
    float* row = scores + ((long)h * SQ + s) * SQ;
    const float* cm = comb + (long)s * SQ;
    __shared__ float red[256];
    float m = NEG_INF;
    for (int t = tid; t < SQ; t += 256)
        if (cm[t] == 0.f) m = fmaxf(m, row[t]);
    red[tid] = m; __syncthreads();
    for (int o = 128; o > 0; o >>= 1) { if (tid < o) red[tid] = fmaxf(red[tid], red[tid + o]); __syncthreads(); }
    m = red[0]; __syncthreads();
    float sum = 0.f;
    for (int t = tid; t < SQ; t += 256) {
        float e = (cm[t] == 0.f) ? expf(row[t] - m) : 0.f;
        row[t] = e; sum += e;
    }
    red[tid] = sum; __syncthreads();
    for (int o = 128; o > 0; o >>= 1) { if (tid < o) red[tid] += red[tid + o]; __syncthreads(); }
    float inv = 1.f / red[0];
    for (int t = tid; t < SQ; t += 256) row[t] *= inv;
}

// ---------------- host orchestration ---------------------------------------
extern "C" void kernel_launch(void* const* d_in, const int* in_sizes, int n_in,
                              void* d_out, int out_size)
{
    if (n_in < 16) return;
    const float *hidden, *wq_a, *q_norm_w, *wq_b, *wkv_a, *kv_norm_w, *wkv_b, *wo;
    const float *idx_wq_b, *idx_wk, *idx_kn_w, *idx_kn_b, *idx_wproj, *fcos, *fsin;
    if (in_sizes[1] == 1536 * 2048) {
        hidden   = (const float*)d_in[0];  wq_a     = (const float*)d_in[1];
        q_norm_w = (const float*)d_in[2];  wq_b     = (const float*)d_in[3];
        wkv_a    = (const float*)d_in[4];  kv_norm_w= (const float*)d_in[5];
        wkv_b    = (const float*)d_in[6];  wo       = (const float*)d_in[7];
        idx_wq_b = (const float*)d_in[8];  idx_wk   = (const float*)d_in[9];
        idx_kn_w = (const float*)d_in[10]; idx_kn_b = (const float*)d_in[11];
        idx_wproj= (const float*)d_in[12]; fcos     = (const float*)d_in[13];
        fsin     = (const float*)d_in[14];
    } else {
        hidden   = (const float*)d_in[0];  fcos     = (const float*)d_in[1];
        fsin     = (const float*)d_in[2];
        wq_a     = (const float*)d_in[4];  q_norm_w = (const float*)d_in[5];
        wq_b     = (const float*)d_in[6];  wkv_a    = (const float*)d_in[7];
        kv_norm_w= (const float*)d_in[8];  wkv_b    = (const float*)d_in[9];
        wo       = (const float*)d_in[10]; idx_wq_b = (const float*)d_in[11];
        idx_wk   = (const float*)d_in[12]; idx_kn_w = (const float*)d_in[13];
        idx_kn_b = (const float*)d_in[14]; idx_wproj= (const float*)d_in[15];
    }

    float *qr, *q, *kvall, *kv, *kvp, *k, *qi, *ki, *wts, *iscore, *comb, *scores, *attnout;
    cudaGetSymbolAddress((void**)&qr, g_qr);
    cudaGetSymbolAddress((void**)&q, g_q);
    cudaGetSymbolAddress((void**)&kvall, g_kvall);
    cudaGetSymbolAddress((void**)&kv, g_kv);
    cudaGetSymbolAddress((void**)&kvp, g_kvp);
    cudaGetSymbolAddress((void**)&k, g_k);
    cudaGetSymbolAddress((void**)&qi, g_qi);
    cudaGetSymbolAddress((void**)&ki, g_ki);
    cudaGetSymbolAddress((void**)&wts, g_wts);
    cudaGetSymbolAddress((void**)&iscore, g_iscore);
    cudaGetSymbolAddress((void**)&comb, g_comb);
    cudaGetSymbolAddress((void**)&scores, g_scores);
    cudaGetSymbolAddress((void**)&attnout, g_attnout);
    float* outp = (float*)d_out;

    dim3 blk(16, 16);
    const float inv_sqrt192 = 0.07216878364870323f;
    const float inv_sqrt32  = 0.17677669529663687f;

    // 1) qr_pre = hidden @ wq_a^T
    gemm_nt_k<<<dim3(QRR/128, SQ/128, 1), blk>>>(hidden, 0, DMM, wq_a, 0, DMM, qr, 0, QRR,
                                                 SQ, QRR, DMM, 1.f, 0);
    // 2) rmsnorm qr (in place)
    rmsnorm_k<<<SQ, 256>>>(qr, QRR, qr, QRR, q_norm_w, QRR);
    // 3) q = qr @ wq_b^T
    gemm_nt_k<<<dim3(3072/128, SQ/128, 1), blk>>>(qr, 0, QRR, wq_b, 0, QRR, q, 0, 3072,
                                                  SQ, 3072, QRR, 1.f, 0);
    // 4) kv_all = hidden @ wkv_a^T
    gemm_nt_k<<<dim3(5, SQ/128, 1), blk>>>(hidden, 0, DMM, wkv_a, 0, DMM, kvall, 0, 576,
                                           SQ, 576, DMM, 1.f, 0);
    // 5) kv = rmsnorm(kv_all[:, :512])
    rmsnorm_k<<<SQ, 256>>>(kvall, 576, kv, KRR, kv_norm_w, KRR);
    // 6) kvp = kv @ wkv_b^T
    gemm_nt_k<<<dim3(4096/128, SQ/128, 1), blk>>>(kv, 0, KRR, wkv_b, 0, KRR, kvp, 0, 4096,
                                                  SQ, 4096, KRR, 1.f, 0);
    // 7) rope q (in place)
    rope_q_k<<<SQ, 512>>>(q, fcos, fsin);
    // 8) assemble k
    build_k_k<<<dim3(SQ, NH), 128>>>(kvp, kvall, k, fcos, fsin);
    // 9) qi = qr @ idx_wq_b^T
    gemm_nt_k<<<dim3(4096/128, SQ/128, 1), blk>>>(qr, 0, QRR, idx_wq_b, 0, QRR, qi, 0, 4096,
                                                  SQ, 4096, QRR, 1.f, 0);
    // 10) rope_half qi (in place)
    rope_qi_k<<<SQ, 1024>>>(qi, fcos, fsin);
    // 11) ki = hidden @ idx_wk^T
    gemm_nt_k<<<dim3(1, SQ/128, 1), blk>>>(hidden, 0, DMM, idx_wk, 0, DMM, ki, 0, DII,
                                           SQ, DII, DMM, 1.f, 0);
    // 12) layernorm + rope_half ki (in place)
    ln_rope_ki_k<<<SQ, 128>>>(ki, idx_kn_w, idx_kn_b, fcos, fsin);
    // 13) wts = hidden @ idx_wproj^T * HI^-0.5
    gemm_nt_k<<<dim3(1, SQ/128, 1), blk>>>(hidden, 0, DMM, idx_wproj, 0, DMM, wts, 0, HII,
                                           SQ, HII, DMM, inv_sqrt32, 0);
    // 14) indexer scores
    indexer_k<<<dim3(SQ/64, SQ/128), blk>>>(qi, ki, wts, iscore);
    // 15) top-512 -> combined mask
    topk_mask_k<<<SQ, 1024>>>(iscore, comb);
    // 16) attention scores per head (causal)
    gemm_nt_k<<<dim3(SQ/128, SQ/128, NH), blk>>>(q, 192, 3072, k, 192, 3072,
                                                 scores, (long)SQ * SQ, SQ,
                                                 SQ, SQ, 192, inv_sqrt192, 1);
    // 17) masked softmax
    softmax_k<<<dim3(SQ, NH), 256>>>(scores, comb);
    // 18) attn_out = probs @ v
    pv_gemm_k<<<dim3(1, SQ/128, NH), blk>>>(scores, kvp, attnout);
    // 19) out = attn_out @ wo^T
    gemm_nt_k<<<dim3(DMM/128, SQ/128, 1), blk>>>(attnout, 0, DMM, wo, 0, DMM, outp, 0, DMM,
                                                 SQ, DMM, DMM, 1.f, 0);
}

// round 3
// speedup vs baseline: 1.0010x; 1.0010x over previous
#include <cuda_runtime.h>
#include <math.h>

#define SQ 2048           // sequence length
#define NH 16             // attention heads
#define DNN 128           // nope dim
#define DRR 64            // rope dim
#define DVV 128           // v dim
#define QRR 1536
#define KRR 512
#define HII 32            // indexer heads
#define DII 128           // indexer dim
#define TOPK 512
#define DMM 2048

// ---------------- scratch (device globals; no allocation allowed) ----------
__device__ float g_qr   [SQ * QRR];
__device__ float g_q    [SQ * NH * (DNN+DRR)]; // [s,16,192]
__device__ float g_kvall[SQ * (KRR + DRR)];    // [s,576]
__device__ float g_kv   [SQ * KRR];
__device__ float g_kvp  [SQ * NH * (DNN+DVV)]; // [s,16,256]
__device__ float g_k    [SQ * NH * (DNN+DRR)]; // [s,16,192]
__device__ float g_qi   [SQ * HII * DII];      // [s,32,128]
__device__ float g_ki   [SQ * DII];
__device__ float g_wts  [SQ * HII];
__device__ float g_iscore[SQ * SQ];
__device__ float g_comb [SQ * SQ];
__device__ float g_scores[67108864];           // [16, s, t]
__device__ float g_attnout[SQ * DMM];

#define NEG_INF (__int_as_float(0xff800000))

// ===================== 128x128x16 double-buffered NT GEMM ==================
// C = alpha * A @ B^T. A: MxK (lda), B: NxK (ldb), C: MxN (ldc). batch via z.
__global__ __launch_bounds__(256) void gemm_nt_k(
    const float* __restrict__ A, long sa, int lda,
    const float* __restrict__ B, long sb, int ldb,
    float* __restrict__ C, long sc, int ldc,
    int M, int N, int K, float alpha, int causal)
{
    A += (long)blockIdx.z * sa; B += (long)blockIdx.z * sb; C += (long)blockIdx.z * sc;
    int n0 = blockIdx.x * 128, m0 = blockIdx.y * 128;
    if (causal && n0 > m0 + 127) return;

    __shared__ float As[2][16][128];
    __shared__ float Bs[2][16][128];

    int tx = threadIdx.x, ty = threadIdx.y;
    int tid = ty * 16 + tx;
    int lrow = tid >> 1;            // 0..127
    int lcol = (tid & 1) * 8;       // 0 or 8

    const float* Ap = A + (long)(m0 + lrow) * lda + lcol;
    const float* Bp = B + (long)(n0 + lrow) * ldb + lcol;
    bool aval = (m0 + lrow) < M;
    bool bval = (n0 + lrow) < N;

    float4 ra0, ra1, rb0, rb1;
    const float4 z4 = make_float4(0.f, 0.f, 0.f, 0.f);

    // prologue: load k-tile 0
    ra0 = aval ? *(const float4*)(Ap)     : z4;
    ra1 = aval ? *(const float4*)(Ap + 4) : z4;
    rb0 = bval ? *(const float4*)(Bp)     : z4;
    rb1 = bval ? *(const float4*)(Bp + 4) : z4;
    As[0][lcol+0][lrow]=ra0.x; As[0][lcol+1][lrow]=ra0.y; As[0][lcol+2][lrow]=ra0.z; As[0][lcol+3][lrow]=ra0.w;
    As[0][lcol+4][lrow]=ra1.x; As[0][lcol+5][lrow]=ra1.y; As[0][lcol+6][lrow]=ra1.z; As[0][lcol+7][lrow]=ra1.w;
    Bs[0][lcol+0][lrow]=rb0.x; Bs[0][lcol+1][lrow]=rb0.y; Bs[0][lcol+2][lrow]=rb0.z; Bs[0][lcol+3][lrow]=rb0.w;
    Bs[0][lcol+4][lrow]=rb1.x; Bs[0][lcol+5][lrow]=rb1.y; Bs[0][lcol+6][lrow]=rb1.z; Bs[0][lcol+7][lrow]=rb1.w;
    __syncthreads();

    float acc[8][8] = {};
    int nk = K >> 4;
    for (int kt = 0; kt < nk; kt++) {
        int cur = kt & 1;
        if (kt + 1 < nk) {
            const float* Ap2 = Ap + (kt + 1) * 16;
            const float* Bp2 = Bp + (kt + 1) * 16;
            ra0 = aval ? *(const float4*)(Ap2)     : z4;
            ra1 = aval ? *(const float4*)(Ap2 + 4) : z4;
            rb0 = bval ? *(const float4*)(Bp2)     : z4;
            rb1 = bval ? *(const float4*)(Bp2 + 4) : z4;
        }
        #pragma unroll
        for (int k = 0; k < 16; k++) {
            float4 a0 = *(const float4*)(&As[cur][k][ty * 8]);
            float4 a1 = *(const float4*)(&As[cur][k][ty * 8 + 4]);
            float4 b0 = *(const float4*)(&Bs[cur][k][tx * 8]);
            float4 b1 = *(const float4*)(&Bs[cur][k][tx * 8 + 4]);
            float a[8] = {a0.x,a0.y,a0.z,a0.w,a1.x,a1.y,a1.z,a1.w};
            float b[8] = {b0.x,b0.y,b0.z,b0.w,b1.x,b1.y,b1.z,b1.w};
            #pragma unroll
            for (int i = 0; i < 8; i++)
                #pragma unroll
                for (int j = 0; j < 8; j++)
                    acc[i][j] += a[i] * b[j];
        }
        if (kt + 1 < nk) {
            int nx = cur ^ 1;
            As[nx][lcol+0][lrow]=ra0.x; As[nx][lcol+1][lrow]=ra0.y; As[nx][lcol+2][lrow]=ra0.z; As[nx][lcol+3][lrow]=ra0.w;
            As[nx][lcol+4][lrow]=ra1.x; As[nx][lcol+5][lrow]=ra1.y; As[nx][lcol+6][lrow]=ra1.z; As[nx][lcol+7][lrow]=ra1.w;
            Bs[nx][lcol+0][lrow]=rb0.x; Bs[nx][lcol+1][lrow]=rb0.y; Bs[nx][lcol+2][lrow]=rb0.z; Bs[nx][lcol+3][lrow]=rb0.w;
            Bs[nx][lcol+4][lrow]=rb1.x; Bs[nx][lcol+5][lrow]=rb1.y; Bs[nx][lcol+6][lrow]=rb1.z; Bs[nx][lcol+7][lrow]=rb1.w;
        }
        __syncthreads();
    }

    #pragma unroll
    for (int i = 0; i < 8; i++) {
        int m = m0 + ty * 8 + i;
        if (m >= M) continue;
        int n = n0 + tx * 8;
        if (n < N) {
            float4 o0 = make_float4(acc[i][0]*alpha, acc[i][1]*alpha, acc[i][2]*alpha, acc[i][3]*alpha);
            float4 o1 = make_float4(acc[i][4]*alpha, acc[i][5]*alpha, acc[i][6]*alpha, acc[i][7]*alpha);
            *(float4*)(C + (long)m * ldc + n)     = o0;
            *(float4*)(C + (long)m * ldc + n + 4) = o1;
        }
    }
}

// ===================== PV GEMM: out[.,h,:] = probs_h @ v_h (NN) ============
__global__ __launch_bounds__(256) void pv_gemm_k(
    const float* __restrict__ probs, const float* __restrict__ kvp,
    float* __restrict__ out)
{
    int h = blockIdx.z;
    const float* A = probs + (long)h * SQ * SQ;     // [m][k], lda=SQ
    const float* B = kvp + h * 256 + 128;           // [k][n], ldb=4096
    float* C = out + h * 128;                       // ldc=2048
    int m0 = blockIdx.y * 128;                      // n0 = 0 (N=128)
    int Kmax = m0 + 128;                            // probs zero beyond diag

    __shared__ float As[2][16][128];
    __shared__ float Bs[2][16][128];

    int tx = threadIdx.x, ty = threadIdx.y;
    int tid = ty * 16 + tx;
    int arow = tid >> 1, acol = (tid & 1) * 8;      // A: 128 m x 16 k
    int brow = tid >> 4, bcol = (tid & 15) * 8;     // B: 16 k x 128 n

    const float* Ap = A + (long)(m0 + arow) * SQ + acol;
    const float* Bp = B + (long)brow * 4096 + bcol;

    float4 ra0, ra1, rb0, rb1;
    ra0 = *(const float4*)(Ap);
    ra1 = *(const float4*)(Ap + 4);
    rb0 = *(const float4*)(Bp);
    rb1 = *(const float4*)(Bp + 4);
    As[0][acol+0][arow]=ra0.x; As[0][acol+1][arow]=ra0.y; As[0][acol+2][arow]=ra0.z; As[0][acol+3][arow]=ra0.w;
    As[0][acol+4][arow]=ra1.x; As[0][acol+5][arow]=ra1.y; As[0][acol+6][arow]=ra1.z; As[0][acol+7][arow]=ra1.w;
    *(float4*)(&Bs[0][brow][bcol])   = rb0;
    *(float4*)(&Bs[0][brow][bcol+4]) = rb1;
    __syncthreads();

    float acc[8][8] = {};
    int nk = Kmax >> 4;
    for (int kt = 0; kt < nk; kt++) {
        int cur = kt & 1;
        if (kt + 1 < nk) {
            const float* Ap2 = Ap + (kt + 1) * 16;
            const float* Bp2 = Bp + (long)(kt + 1) * 16 * 4096;
            ra0 = *(const float4*)(Ap2);
            ra1 = *(const float4*)(Ap2 + 4);
            rb0 = *(const float4*)(Bp2);
            rb1 = *(const float4*)(Bp2 + 4);
        }
        #pragma unroll
        for (int k = 0; k < 16; k++) {
            float4 a0 = *(const float4*)(&As[cur][k][ty * 8]);
            float4 a1 = *(const float4*)(&As[cur][k][ty * 8 + 4]);
            float4 b0 = *(const float4*)(&Bs[cur][k][tx * 8]);
            float4 b1 = *(const float4*)(&Bs[cur][k][tx * 8 + 4]);
            float a[8] = {a0.x,a0.y,a0.z,a0.w,a1.x,a1.y,a1.z,a1.w};
            float b[8] = {b0.x,b0.y,b0.z,b0.w,b1.x,b1.y,b1.z,b1.w};
            #pragma unroll
            for (int i = 0; i < 8; i++)
                #pragma unroll
                for (int j = 0; j < 8; j++)
                    acc[i][j] += a[i] * b[j];
        }
        if (kt + 1 < nk) {
            int nx = cur ^ 1;
            As[nx][acol+0][arow]=ra0.x; As[nx][acol+1][arow]=ra0.y; As[nx][acol+2][arow]=ra0.z; As[nx][acol+3][arow]=ra0.w;
            As[nx][acol+4][arow]=ra1.x; As[nx][acol+5][arow]=ra1.y; As[nx][acol+6][arow]=ra1.z; As[nx][acol+7][arow]=ra1.w;
            *(float4*)(&Bs[nx][brow][bcol])   = rb0;
            *(float4*)(&Bs[nx][brow][bcol+4]) = rb1;
        }
        __syncthreads();
    }

    #pragma unroll
    for (int i = 0; i < 8; i++) {
        int m = m0 + ty * 8 + i;
        float4 o0 = make_float4(acc[i][0], acc[i][1], acc[i][2], acc[i][3]);
        float4 o1 = make_float4(acc[i][4], acc[i][5], acc[i][6], acc[i][7]);
        *(float4*)(C + (long)m * 2048 + tx * 8)     = o0;
        *(float4*)(C + (long)m * 2048 + tx * 8 + 4) = o1;
    }
}

// ---------------- rmsnorm (per row) ----------------------------------------
__global__ void rmsnorm_k(const float* __restrict__ in, int ldi,
                          float* __restrict__ out, int ldo,
                          const float* __restrict__ w, int D)
{
    int s = blockIdx.x, tid = threadIdx.x;
    __shared__ float red[256];
    const float* ip = in + (long)s * ldi;
    float ss = 0.f;
    for (int d = tid; d < D; d += 256) { float v = ip[d]; ss += v * v; }
    red[tid] = ss; __syncthreads();
    for (int o = 128; o > 0; o >>= 1) { if (tid < o) red[tid] += red[tid + o]; __syncthreads(); }
    float scale = rsqrtf(red[0] / (float)D + 1e-6f);
    float* op = out + (long)s * ldo;
    for (int d = tid; d < D; d += 256) op[d] = ip[d] * scale * w[d];
}

// ---------------- rope (interleaved) on q's last 64 dims, in-place --------
__global__ void rope_q_k(float* __restrict__ q,
                         const float* __restrict__ cs, const float* __restrict__ sn)
{
    int s = blockIdx.x;
    int tid = threadIdx.x;       // 512 = 16 heads * 32 pairs
    int h = tid >> 5, i = tid & 31;
    float c = cs[s * 32 + i], si = sn[s * 32 + i];
    float* p = q + (long)s * 3072 + h * 192 + 128 + 2 * i;
    float x0 = p[0], x1 = p[1];
    p[0] = x0 * c - x1 * si;
    p[1] = x0 * si + x1 * c;
}

// ---------------- assemble k = [kvp[...,:128], rope(k_pe)] -----------------
__global__ void build_k_k(const float* __restrict__ kvp, const float* __restrict__ kvall,
                          float* __restrict__ kk,
                          const float* __restrict__ cs, const float* __restrict__ sn)
{
    int s = blockIdx.x, h = blockIdx.y;
    int tid = threadIdx.x;       // 128
    float* dst = kk + ((long)s * 16 + h) * 192;
    dst[tid] = kvp[(long)s * 4096 + h * 256 + tid];
    if (tid < 32) {
        float c = cs[s * 32 + tid], si = sn[s * 32 + tid];
        float x0 = kvall[(long)s * 576 + 512 + 2 * tid];
        float x1 = kvall[(long)s * 576 + 513 + 2 * tid];
        dst[128 + 2 * tid] = x0 * c - x1 * si;
        dst[129 + 2 * tid] = x0 * si + x1 * c;
    }
}

// ---------------- rope_half on qi first 64 dims per head, in-place --------
__global__ void rope_qi_k(float* __restrict__ qi,
                          const float* __restrict__ cs, const float* __restrict__ sn)
{
    int s = blockIdx.x;
    int tid = threadIdx.x;       // 1024 = 32 heads * 32 dims
    int h = tid >> 5, d = tid & 31;
    float c = cs[s * 32 + d], si = sn[s * 32 + d];
    float* p = qi + (long)s * 4096 + h * 128;
    float x0 = p[d], x1 = p[d + 32];
    p[d] = x0 * c - x1 * si;
    p[d + 32] = x0 * si + x1 * c;
}

// ---------------- layernorm + rope_half for ki (in-place, width 128) ------
__global__ void ln_rope_ki_k(float* __restrict__ ki,
                             const float* __restrict__ w, const float* __restrict__ b,
                             const float* __restrict__ cs, const float* __restrict__ sn)
{
    int s = blockIdx.x, tid = threadIdx.x;   // 128
    __shared__ float red[128];
    __shared__ float buf[128];
    float v = ki[(long)s * 128 + tid];
    red[tid] = v; __syncthreads();
    for (int o = 64; o > 0; o >>= 1) { if (tid < o) red[tid] += red[tid + o]; __syncthreads(); }
    float mean = red[0] / 128.f; __syncthreads();
    float d = v - mean;
    red[tid] = d * d; __syncthreads();
    for (int o = 64; o > 0; o >>= 1) { if (tid < o) red[tid] += red[tid + o]; __syncthreads(); }
    float var = red[0] / 128.f;
    float nv = d * rsqrtf(var + 1e-5f) * w[tid] + b[tid];
    buf[tid] = nv; __syncthreads();
    float out;
    if (tid < 32) {
        float c = cs[s * 32 + tid], si = sn[s * 32 + tid];
        out = buf[tid] * c - buf[tid + 32] * si;
    } else if (tid < 64) {
        int i = tid - 32;
        float c = cs[s * 32 + i], si = sn[s * 32 + i];
        out = buf[i] * si + buf[i + 32] * c;
    } else {
        out = nv;
    }
    ki[(long)s * 128 + tid] = out;
}

// =============== indexer: sum_h relu(qi_h . ki / sqrt(128)) * w ============
// tile: 128 s-rows x 64 t-cols; ki tile resident in smem across 32 heads.
__global__ __launch_bounds__(256) void indexer_k(
    const float* __restrict__ qi, const float* __restrict__ ki,
    const float* __restrict__ wts, float* __restrict__ out)
{
    int t0 = blockIdx.x * 64, s0 = blockIdx.y * 128;
    if (t0 > s0 + 127) return;

    __shared__ float Bs[128][64];   // ki [k][t]  32KB
    __shared__ float As[16][128];   // qi chunk [k][s]  8KB
    __shared__ float Ws[128][16];   // wts group [s][h] 8KB

    int tx = threadIdx.x, ty = threadIdx.y;
    int tid = ty * 16 + tx;

    // load ki tile (transposed)
    {
        int t = tid >> 2, kb = (tid & 3) * 32;
        const float* kp = ki + (long)(t0 + t) * 128 + kb;
        #pragma unroll
        for (int c = 0; c < 32; c += 4) {
            float4 v = *(const float4*)(kp + c);
            Bs[kb+c][t] = v.x; Bs[kb+c+1][t] = v.y; Bs[kb+c+2][t] = v.z; Bs[kb+c+3][t] = v.w;
        }
    }

    const float scl = 0.08838834764831845f;  // 1/sqrt(128)
    float fin[8][4] = {};
    int arow = tid >> 1, acol = (tid & 1) * 8;

    for (int hg = 0; hg < 2; hg++) {
        __syncthreads();   // Bs ready (first iter) / Ws reuse safe
        for (int i = tid; i < 2048; i += 256)
            Ws[i >> 4][i & 15] = wts[(long)(s0 + (i >> 4)) * 32 + hg * 16 + (i & 15)];
        __syncthreads();

        for (int hh = 0; hh < 16; hh++) {
            int h = hg * 16 + hh;
            float acc[8][4] = {};
            #pragma unroll
            for (int kc = 0; kc < 8; kc++) {
                const float* qp = qi + (long)(s0 + arow) * 4096 + h * 128 + kc * 16 + acol;
                float4 v0 = *(const float4*)(qp);
                float4 v1 = *(const float4*)(qp + 4);
                __syncthreads();   // previous chunk consumed
                As[acol+0][arow]=v0.x; As[acol+1][arow]=v0.y; As[acol+2][arow]=v0.z; As[acol+3][arow]=v0.w;
                As[acol+4][arow]=v1.x; As[acol+5][arow]=v1.y; As[acol+6][arow]=v1.z; As[acol+7][arow]=v1.w;
                __syncthreads();
                #pragma unroll
                for (int k = 0; k < 16; k++) {
                    float4 a0 = *(const float4*)(&As[k][ty * 8]);
                    float4 a1 = *(const float4*)(&As[k][ty * 8 + 4]);
                    float4 b4 = *(const float4*)(&Bs[kc * 16 + k][tx * 4]);
                    float a[8] = {a0.x,a0.y,a0.z,a0.w,a1.x,a1.y,a1.z,a1.w};
                    float b[4] = {b4.x,b4.y,b4.z,b4.w};
                    #pragma unroll
                    for (int i = 0; i < 8; i++)
                        #pragma unroll
                        for (int j = 0; j < 4; j++)
                            acc[i][j] += a[i] * b[j];
                }
            }
            #pragma unroll
            for (int i = 0; i < 8; i++) {
                float wv = Ws[ty * 8 + i][hh];
                #pragma unroll
                for (int j = 0; j < 4; j++)
                    fin[i][j] += fmaxf(acc[i][j] * scl, 0.f) * wv;
            }
        }
    }

    #pragma unroll
    for (int i = 0; i < 8; i++) {
        float4 o = make_float4(fin[i][0], fin[i][1], fin[i][2], fin[i][3]);
        *(float4*)(out + (long)(s0 + ty * 8 + i) * SQ + t0 + tx * 4) = o;
    }
}

// ---------------- per-row top-512 -> combined mask (0 keep / -inf drop) ---
__global__ __launch_bounds__(1024) void topk_mask_k(
    const float* __restrict__ iscore, float* __restrict__ comb)
{
    int s = blockIdx.x, tid = threadIdx.x;
    __shared__ float sv[2048];
    __shared__ float xo[2048];
    __shared__ unsigned char sel[2048];
    __shared__ int s_cnt;
    for (int t = tid; t < 2048; t += 1024) {
        float v = (t <= s) ? iscore[(long)s * SQ + t] : NEG_INF;
        xo[t] = v; sv[t] = v; sel[t] = 0;
    }
    if (tid == 0) s_cnt = 0;
    __syncthreads();

    if (s <= TOPK - 1) {  // <=512 causal entries: keep all
        for (int t = tid; t < 2048; t += 1024)
            comb[(long)s * SQ + t] = (t <= s) ? 0.f : NEG_INF;
        return;
    }
    // bitonic sort ascending
    for (int k = 2; k <= 2048; k <<= 1) {
        for (int j = k >> 1; j > 0; j >>= 1) {
            for (int t = tid; t < 2048; t += 1024) {
                int ixj = t ^ j;
                if (ixj > t) {
                    float a = sv[t], b = sv[ixj];
                    bool asc = ((t & k) == 0);
                    if (asc ? (a > b) : (a < b)) { sv[t] = b; sv[ixj] = a; }
                }
            }
            __syncthreads();
        }
    }
    float T = sv[2048 - TOPK];   // 512th largest
    int local = 0;
    for (int t = tid; t <= s; t += 1024)
        if (xo[t] > T) { sel[t] = 1; local++; }
    atomicAdd(&s_cnt, local);
    __syncthreads();
    if (tid == 0) {
        int quota = TOPK - s_cnt;    // ties at T by lowest index (jax tie-break)
        for (int t = 0; t <= s && quota > 0; t++)
            if (!sel[t] && xo[t] == T) { sel[t] = 1; quota--; }
    }
    __syncthreads();
    for (int t = tid; t < 2048; t += 1024)
        comb[(long)s * SQ + t] = sel[t] ? 0.f : NEG_INF;
}

// ---------------- masked softmax over t, in-place on g_scores --------------
__global__ void softmax_k(float* __restrict__ scores, const float* __restrict__ comb)
{
    int s = blockIdx.x, h = blockIdx.y, tid = threadIdx.x;
    float* row = scores + ((long)h * SQ + s) * SQ;
    const float* cm = comb + (long)s * SQ;
    __shared__ float red[256];
    float m = NEG_INF;
    for (int t = tid; t < SQ; t += 256)
        if (cm[t] == 0.f) m = fmaxf(m, row[t]);
    red[tid] = m; __syncthreads();
    for (int o = 128; o > 0; o >>= 1) { if (tid < o) red[tid] = fmaxf(red[tid], red[tid + o]); __syncthreads(); }
    m = red[0]; __syncthreads();
    float sum = 0.f;
    for (int t = tid; t < SQ; t += 256) {
        float e = (cm[t] == 0.f) ? expf(row[t] - m) : 0.f;
        row[t] = e; sum += e;
    }
    red[tid] = sum; __syncthreads();
    for (int o = 128; o > 0; o >>= 1) { if (tid < o) red[tid] += red[tid + o]; __syncthreads(); }
    float inv = 1.f / red[0];
    for (int t = tid; t < SQ; t += 256) row[t] *= inv;
}

// ---------------- host orchestration ---------------------------------------
extern "C" void kernel_launch(void* const* d_in, const int* in_sizes, int n_in,
                              void* d_out, int out_size)
{
    if (n_in < 16) return;
    const float *hidden, *wq_a, *q_norm_w, *wq_b, *wkv_a, *kv_norm_w, *wkv_b, *wo;
    const float *idx_wq_b, *idx_wk, *idx_kn_w, *idx_kn_b, *idx_wproj, *fcos, *fsin;
    if (in_sizes[1] == 1536 * 2048) {
        hidden   = (const float*)d_in[0];  wq_a     = (const float*)d_in[1];
        q_norm_w = (const float*)d_in[2];  wq_b     = (const float*)d_in[3];
        wkv_a    = (const float*)d_in[4];  kv_norm_w= (const float*)d_in[5];
        wkv_b    = (const float*)d_in[6];  wo       = (const float*)d_in[7];
        idx_wq_b = (const float*)d_in[8];  idx_wk   = (const float*)d_in[9];
        idx_kn_w = (const float*)d_in[10]; idx_kn_b = (const float*)d_in[11];
        idx_wproj= (const float*)d_in[12]; fcos     = (const float*)d_in[13];
        fsin     = (const float*)d_in[14];
    } else {
        hidden   = (const float*)d_in[0];  fcos     = (const float*)d_in[1];
        fsin     = (const float*)d_in[2];
        wq_a     = (const float*)d_in[4];  q_norm_w = (const float*)d_in[5];
        wq_b     = (const float*)d_in[6];  wkv_a    = (const float*)d_in[7];
        kv_norm_w= (const float*)d_in[8];  wkv_b    = (const float*)d_in[9];
        wo       = (const float*)d_in[10]; idx_wq_b = (const float*)d_in[11];
        idx_wk   = (const float*)d_in[12]; idx_kn_w = (const float*)d_in[13];
        idx_kn_b = (const float*)d_in[14]; idx_wproj= (const float*)d_in[15];
    }

    float *qr, *q, *kvall, *kv, *kvp, *k, *qi, *ki, *wts, *iscore, *comb, *scores, *attnout;
    cudaGetSymbolAddress((void**)&qr, g_qr);
    cudaGetSymbolAddress((void**)&q, g_q);
    cudaGetSymbolAddress((void**)&kvall, g_kvall);
    cudaGetSymbolAddress((void**)&kv, g_kv);
    cudaGetSymbolAddress((void**)&kvp, g_kvp);
    cudaGetSymbolAddress((void**)&k, g_k);
    cudaGetSymbolAddress((void**)&qi, g_qi);
    cudaGetSymbolAddress((void**)&ki, g_ki);
    cudaGetSymbolAddress((void**)&wts, g_wts);
    cudaGetSymbolAddress((void**)&iscore, g_iscore);
    cudaGetSymbolAddress((void**)&comb, g_comb);
    cudaGetSymbolAddress((void**)&scores, g_scores);
    cudaGetSymbolAddress((void**)&attnout, g_attnout);
    float* outp = (float*)d_out;

    dim3 blk(16, 16);
    const float inv_sqrt192 = 0.07216878364870323f;
    const float inv_sqrt32  = 0.17677669529663687f;

    // 1) qr_pre = hidden @ wq_a^T
    gemm_nt_k<<<dim3(QRR/128, SQ/128, 1), blk>>>(hidden, 0, DMM, wq_a, 0, DMM, qr, 0, QRR,
                                                 SQ, QRR, DMM, 1.f, 0);
    // 2) rmsnorm qr (in place)
    rmsnorm_k<<<SQ, 256>>>(qr, QRR, qr, QRR, q_norm_w, QRR);
    // 3) q = qr @ wq_b^T
    gemm_nt_k<<<dim3(3072/128, SQ/128, 1), blk>>>(qr, 0, QRR, wq_b, 0, QRR, q, 0, 3072,
                                                  SQ, 3072, QRR, 1.f, 0);
    // 4) kv_all = hidden @ wkv_a^T
    gemm_nt_k<<<dim3(5, SQ/128, 1), blk>>>(hidden, 0, DMM, wkv_a, 0, DMM, kvall, 0, 576,
                                           SQ, 576, DMM, 1.f, 0);
    // 5) kv = rmsnorm(kv_all[:, :512])
    rmsnorm_k<<<SQ, 256>>>(kvall, 576, kv, KRR, kv_norm_w, KRR);
    // 6) kvp = kv @ wkv_b^T
    gemm_nt_k<<<dim3(4096/128, SQ/128, 1), blk>>>(kv, 0, KRR, wkv_b, 0, KRR, kvp, 0, 4096,
                                                  SQ, 4096, KRR, 1.f, 0);
    // 7) rope q (in place)
    rope_q_k<<<SQ, 512>>>(q, fcos, fsin);
    // 8) assemble k
    build_k_k<<<dim3(SQ, NH), 128>>>(kvp, kvall, k, fcos, fsin);
    // 9) qi = qr @ idx_wq_b^T
    gemm_nt_k<<<dim3(4096/128, SQ/128, 1), blk>>>(qr, 0, QRR, idx_wq_b, 0, QRR, qi, 0, 4096,
                                                  SQ, 4096, QRR, 1.f, 0);
    // 10) rope_half qi (in place)
    rope_qi_k<<<SQ, 1024>>>(qi, fcos, fsin);
    // 11) ki = hidden @ idx_wk^T
    gemm_nt_k<<<dim3(1, SQ/128, 1), blk>>>(hidden, 0, DMM, idx_wk, 0, DMM, ki, 0, DII,
                                           SQ, DII, DMM, 1.f, 0);
    // 12) layernorm + rope_half ki (in place)
    ln_rope_ki_k<<<SQ, 128>>>(ki, idx_kn_w, idx_kn_b, fcos, fsin);
    // 13) wts = hidden @ idx_wproj^T * HI^-0.5
    gemm_nt_k<<<dim3(1, SQ/128, 1), blk>>>(hidden, 0, DMM, idx_wproj, 0, DMM, wts, 0, HII,
                                           SQ, HII, DMM, inv_sqrt32, 0);
    // 14) indexer scores
    indexer_k<<<dim3(SQ/64, SQ/128), blk>>>(qi, ki, wts, iscore);
    // 15) top-512 -> combined mask
    topk_mask_k<<<SQ, 1024>>>(iscore, comb);
    // 16) attention scores per head (causal)
    gemm_nt_k<<<dim3(SQ/128, SQ/128, NH), blk>>>(q, 192, 3072, k, 192, 3072,
                                                 scores, (long)SQ * SQ, SQ,
                                                 SQ, SQ, 192, inv_sqrt192, 1);
    // 17) masked softmax
    softmax_k<<<dim3(SQ, NH), 256>>>(scores, comb);
    // 18) attn_out = probs @ v
    pv_gemm_k<<<dim3(1, SQ/128, NH), blk>>>(scores, kvp, attnout);
    // 19) out = attn_out @ wo^T
    gemm_nt_k<<<dim3(DMM/128, SQ/128, 1), blk>>>(attnout, 0, DMM, wo, 0, DMM, outp, 0, DMM,
                                                 SQ, DMM, DMM, 1.f, 0);
}

// round 6
// speedup vs baseline: 1.2769x; 1.2756x over previous
#include <cuda_runtime.h>
#include <cuda_bf16.h>
#include <math.h>
#include <stdint.h>

#define SQ 2048
#define NH 16
#define QRR 1536
#define KRR 512
#define TOPK 512
#define DMM 2048
#define NEG_INF (__int_as_float(0xff800000))
typedef __nv_bfloat16 bf16;

// ---------------- fp32 scratch ----------------
__device__ float g_qr[SQ*QRR];
__device__ float g_q[SQ*NH*192];
__device__ float g_kvall[SQ*576];
__device__ float g_kv[SQ*KRR];
__device__ float g_kvp[SQ*NH*256];
__device__ float g_k[SQ*NH*192];
__device__ float g_qi[SQ*32*128];
__device__ float g_ki[SQ*128];
__device__ float g_wts[SQ*32];
__device__ float g_iscore[SQ*SQ];
__device__ float g_comb[SQ*SQ];
__device__ float g_scores[67108864];
__device__ float g_attnout[SQ*DMM];
// ---------------- bf16 hi/lo scratch (smooth path only) ----------------
__device__ bf16 g_h_hi[2048*2048],  g_h_lo[2048*2048];
__device__ bf16 g_wqb_hi[3072*1536],g_wqb_lo[3072*1536];
__device__ bf16 g_wkva_hi[576*2048],g_wkva_lo[576*2048];
__device__ bf16 g_wkvb_hi[4096*512],g_wkvb_lo[4096*512];
__device__ bf16 g_wo_hi[2048*2048], g_wo_lo[2048*2048];
__device__ bf16 g_qrn_hi[2048*1536],g_qrn_lo[2048*1536];
__device__ bf16 g_kvn_hi[2048*512], g_kvn_lo[2048*512];
__device__ bf16 g_qh_hi[2048*3072], g_qh_lo[2048*3072];
__device__ bf16 g_kh_hi[2048*3072], g_kh_lo[2048*3072];
__device__ bf16 g_at_hi[2048*2048], g_at_lo[2048*2048];

// ================= mma.sync helpers =================
__device__ __forceinline__ uint32_t smem_u32(const void* p){
    uint32_t a; asm("{ .reg .u64 t; cvta.to.shared.u64 t, %1; cvt.u32.u64 %0, t; }":"=r"(a):"l"(p)); return a;
}
#define LDSM4(R, ADDR) asm volatile( \
    "ldmatrix.sync.aligned.m8n8.x4.shared.b16 {%0,%1,%2,%3}, [%4];" \
    : "=r"((R)[0]),"=r"((R)[1]),"=r"((R)[2]),"=r"((R)[3]) : "r"(ADDR))
#define MMA16816(D, A, B) asm volatile( \
    "mma.sync.aligned.m16n8k16.row.col.f32.bf16.bf16.f32 " \
    "{%0,%1,%2,%3}, {%4,%5,%6,%7}, {%8,%9}, {%0,%1,%2,%3};" \
    : "+f"((D)[0]),"+f"((D)[1]),"+f"((D)[2]),"+f"((D)[3]) \
    : "r"((A)[0]),"r"((A)[1]),"r"((A)[2]),"r"((A)[3]), "r"((B)[0]),"r"((B)[1]))

// ======= bf16x3 NT GEMM via mma.sync (smooth path) =======
#define LSTR 72
#define MMA_SMEM (4*128*LSTR*2)
__global__ __launch_bounds__(256) void gemm_mma_nt(
    const bf16* __restrict__ Ah, const bf16* __restrict__ Al, long sa, int lda,
    const bf16* __restrict__ Bh, const bf16* __restrict__ Bl, long sb, int ldb,
    float* __restrict__ C, long sc, int ldc, int N, int K, float alpha, int causal)
{
    int n0 = blockIdx.x*128, m0 = blockIdx.y*128;
    if (causal && n0 > m0+127) return;
    Ah += (long)blockIdx.z*sa; Al += (long)blockIdx.z*sa;
    Bh += (long)blockIdx.z*sb; Bl += (long)blockIdx.z*sb;
    C  += (long)blockIdx.z*sc;

    extern __shared__ bf16 sm[];
    bf16 *sAh = sm, *sAl = sm + 128*LSTR, *sBh = sm + 2*128*LSTR, *sBl = sm + 3*128*LSTR;
    int tid = threadIdx.x, lane = tid & 31, wid = tid >> 5;
    int wm = (wid >> 1) * 32, wn = (wid & 1) * 64;
    float acc[2][8][4] = {};

    for (int kc = 0; kc < K; kc += 64){
        __syncthreads();
        #pragma unroll
        for (int it = 0; it < 4; it++){
            int c = tid + it*256, row = c >> 3, cb = (c & 7) * 8;
            long ga = (long)(m0+row)*lda + kc + cb;
            *(int4*)&sAh[row*LSTR + cb] = *(const int4*)(Ah + ga);
            *(int4*)&sAl[row*LSTR + cb] = *(const int4*)(Al + ga);
            int4 vh = make_int4(0,0,0,0), vl = vh;
            if (n0 + row < N){
                long gb = (long)(n0+row)*ldb + kc + cb;
                vh = *(const int4*)(Bh + gb); vl = *(const int4*)(Bl + gb);
            }
            *(int4*)&sBh[row*LSTR + cb] = vh;
            *(int4*)&sBl[row*LSTR + cb] = vl;
        }
        __syncthreads();

        int r = lane & 15, ko = (lane >> 4) * 8;
        #pragma unroll
        for (int ks = 0; ks < 4; ks++){
            uint32_t ah[2][4], al[2][4], bh[8][2], bl[8][2];
            #pragma unroll
            for (int mi = 0; mi < 2; mi++){
                uint32_t ad = smem_u32(&sAh[(wm + mi*16 + r)*LSTR + ks*16 + ko]);
                LDSM4(ah[mi], ad);
                ad = smem_u32(&sAl[(wm + mi*16 + r)*LSTR + ks*16 + ko]);
                LDSM4(al[mi], ad);
            }
            #pragma unroll
            for (int np = 0; np < 4; np++){
                uint32_t t4[4];
                uint32_t bd = smem_u32(&sBh[(wn + np*16 + r)*LSTR + ks*16 + ko]);
                LDSM4(t4, bd);
                bh[2*np][0]=t4[0]; bh[2*np][1]=t4[2]; bh[2*np+1][0]=t4[1]; bh[2*np+1][1]=t4[3];
                bd = smem_u32(&sBl[(wn + np*16 + r)*LSTR + ks*16 + ko]);
                LDSM4(t4, bd);
                bl[2*np][0]=t4[0]; bl[2*np][1]=t4[2]; bl[2*np+1][0]=t4[1]; bl[2*np+1][1]=t4[3];
            }
            #pragma unroll
            for (int mi = 0; mi < 2; mi++)
                #pragma unroll
                for (int ni = 0; ni < 8; ni++){
                    MMA16816(acc[mi][ni], ah[mi], bh[ni]);
                    MMA16816(acc[mi][ni], ah[mi], bl[ni]);
                    MMA16816(acc[mi][ni], al[mi], bh[ni]);
                }
        }
    }
    #pragma unroll
    for (int mi = 0; mi < 2; mi++){
        int mrow = m0 + wm + mi*16 + (lane >> 2);
        #pragma unroll
        for (int ni = 0; ni < 8; ni++){
            int n = n0 + wn + ni*8 + (lane & 3)*2;
            if (n < N){
                *(float2*)(C + (long)mrow*ldc + n)     = make_float2(alpha*acc[mi][ni][0], alpha*acc[mi][ni][1]);
                *(float2*)(C + (long)(mrow+8)*ldc + n) = make_float2(alpha*acc[mi][ni][2], alpha*acc[mi][ni][3]);
            }
        }
    }
}

// ======= fp32 SIMT NT GEMM (bit-identical to passing baseline) =======
__global__ __launch_bounds__(256) void gemm_nt_k(
    const float* __restrict__ A, long sa, int lda,
    const float* __restrict__ B, long sb, int ldb,
    float* __restrict__ C, long sc, int ldc,
    int M, int N, int K, float alpha, int causal)
{
    A += (long)blockIdx.z*sa; B += (long)blockIdx.z*sb; C += (long)blockIdx.z*sc;
    int n0 = blockIdx.x*128, m0 = blockIdx.y*128;
    if (causal && n0 > m0+127) return;
    __shared__ float As[2][16][128];
    __shared__ float Bs[2][16][128];
    int tx = threadIdx.x, ty = threadIdx.y, tid = ty*16+tx;
    int lrow = tid>>1, lcol = (tid&1)*8;
    const float* Ap = A + (long)(m0+lrow)*lda + lcol;
    const float* Bp = B + (long)(n0+lrow)*ldb + lcol;
    bool aval = (m0+lrow) < M, bval = (n0+lrow) < N;
    float4 ra0, ra1, rb0, rb1;
    const float4 z4 = make_float4(0.f,0.f,0.f,0.f);
    ra0 = aval ? *(const float4*)(Ap)   : z4;
    ra1 = aval ? *(const float4*)(Ap+4) : z4;
    rb0 = bval ? *(const float4*)(Bp)   : z4;
    rb1 = bval ? *(const float4*)(Bp+4) : z4;
    As[0][lcol+0][lrow]=ra0.x; As[0][lcol+1][lrow]=ra0.y; As[0][lcol+2][lrow]=ra0.z; As[0][lcol+3][lrow]=ra0.w;
    As[0][lcol+4][lrow]=ra1.x; As[0][lcol+5][lrow]=ra1.y; As[0][lcol+6][lrow]=ra1.z; As[0][lcol+7][lrow]=ra1.w;
    Bs[0][lcol+0][lrow]=rb0.x; Bs[0][lcol+1][lrow]=rb0.y; Bs[0][lcol+2][lrow]=rb0.z; Bs[0][lcol+3][lrow]=rb0.w;
    Bs[0][lcol+4][lrow]=rb1.x; Bs[0][lcol+5][lrow]=rb1.y; Bs[0][lcol+6][lrow]=rb1.z; Bs[0][lcol+7][lrow]=rb1.w;
    __syncthreads();
    float acc[8][8] = {};
    int nk = K>>4;
    for (int kt=0; kt<nk; kt++){
        int cur = kt&1;
        if (kt+1<nk){
            const float* Ap2 = Ap + (kt+1)*16;
            const float* Bp2 = Bp + (kt+1)*16;
            ra0 = aval ? *(const float4*)(Ap2)   : z4;
            ra1 = aval ? *(const float4*)(Ap2+4) : z4;
            rb0 = bval ? *(const float4*)(Bp2)   : z4;
            rb1 = bval ? *(const float4*)(Bp2+4) : z4;
        }
        #pragma unroll
        for (int k=0;k<16;k++){
            float4 a0=*(const float4*)(&As[cur][k][ty*8]);
            float4 a1=*(const float4*)(&As[cur][k][ty*8+4]);
            float4 b0=*(const float4*)(&Bs[cur][k][tx*8]);
            float4 b1=*(const float4*)(&Bs[cur][k][tx*8+4]);
            float a[8]={a0.x,a0.y,a0.z,a0.w,a1.x,a1.y,a1.z,a1.w};
            float b[8]={b0.x,b0.y,b0.z,b0.w,b1.x,b1.y,b1.z,b1.w};
            #pragma unroll
            for (int i=0;i<8;i++)
                #pragma unroll
                for (int j=0;j<8;j++) acc[i][j]+=a[i]*b[j];
        }
        if (kt+1<nk){
            int nx = cur^1;
            As[nx][lcol+0][lrow]=ra0.x; As[nx][lcol+1][lrow]=ra0.y; As[nx][lcol+2][lrow]=ra0.z; As[nx][lcol+3][lrow]=ra0.w;
            As[nx][lcol+4][lrow]=ra1.x; As[nx][lcol+5][lrow]=ra1.y; As[nx][lcol+6][lrow]=ra1.z; As[nx][lcol+7][lrow]=ra1.w;
            Bs[nx][lcol+0][lrow]=rb0.x; Bs[nx][lcol+1][lrow]=rb0.y; Bs[nx][lcol+2][lrow]=rb0.z; Bs[nx][lcol+3][lrow]=rb0.w;
            Bs[nx][lcol+4][lrow]=rb1.x; Bs[nx][lcol+5][lrow]=rb1.y; Bs[nx][lcol+6][lrow]=rb1.z; Bs[nx][lcol+7][lrow]=rb1.w;
        }
        __syncthreads();
    }
    #pragma unroll
    for (int i=0;i<8;i++){
        int m = m0+ty*8+i;
        if (m >= M) continue;
        int n = n0+tx*8;
        if (n < N){
            *(float4*)(C+(long)m*ldc+n)   = make_float4(acc[i][0]*alpha,acc[i][1]*alpha,acc[i][2]*alpha,acc[i][3]*alpha);
            *(float4*)(C+(long)m*ldc+n+4) = make_float4(acc[i][4]*alpha,acc[i][5]*alpha,acc[i][6]*alpha,acc[i][7]*alpha);
        }
    }
}

// ---------------- cvt / norms / ropes ----------------
__global__ void cvt_hilo_k(const float* __restrict__ in, bf16* __restrict__ hi, bf16* __restrict__ lo, int n){
    int i = blockIdx.x*256 + threadIdx.x;
    if (i < n){
        float x = in[i]; bf16 h = __float2bfloat16(x);
        hi[i] = h; lo[i] = __float2bfloat16(x - __bfloat162float(h));
    }
}
__global__ void rmsnorm_k(const float* __restrict__ in, int ldi,
                          float* __restrict__ out, int ldo,
                          const float* __restrict__ w, int D){
    int s = blockIdx.x, tid = threadIdx.x;
    __shared__ float red[256];
    const float* ip = in + (long)s*ldi;
    float ss = 0.f;
    for (int d=tid; d<D; d+=256){ float v = ip[d]; ss += v*v; }
    red[tid]=ss; __syncthreads();
    for (int o=128;o>0;o>>=1){ if(tid<o) red[tid]+=red[tid+o]; __syncthreads(); }
    float scale = rsqrtf(red[0]/(float)D + 1e-6f);
    float* op = out + (long)s*ldo;
    for (int d=tid; d<D; d+=256) op[d] = ip[d]*scale*w[d];
}
__global__ void rope_q_k(float* __restrict__ q, const float* __restrict__ cs, const float* __restrict__ sn){
    int s = blockIdx.x, tid = threadIdx.x, h = tid>>5, i = tid&31;
    float c = cs[s*32+i], si = sn[s*32+i];
    float* p = q + (long)s*3072 + h*192 + 128 + 2*i;
    float x0=p[0], x1=p[1]; p[0]=x0*c-x1*si; p[1]=x0*si+x1*c;
}
__global__ void build_k_k(const float* __restrict__ kvp, const float* __restrict__ kvall,
                          float* __restrict__ kk, const float* __restrict__ cs, const float* __restrict__ sn){
    int s = blockIdx.x, h = blockIdx.y, tid = threadIdx.x;
    float* dst = kk + ((long)s*16+h)*192;
    dst[tid] = kvp[(long)s*4096 + h*256 + tid];
    if (tid < 32){
        float c = cs[s*32+tid], si = sn[s*32+tid];
        float x0 = kvall[(long)s*576+512+2*tid], x1 = kvall[(long)s*576+513+2*tid];
        dst[128+2*tid]=x0*c-x1*si; dst[129+2*tid]=x0*si+x1*c;
    }
}
__global__ void rope_qi_k(float* __restrict__ qi, const float* __restrict__ cs, const float* __restrict__ sn){
    int s = blockIdx.x, tid = threadIdx.x, h = tid>>5, d = tid&31;
    float c = cs[s*32+d], si = sn[s*32+d];
    float* p = qi + (long)s*4096 + h*128;
    float x0=p[d], x1=p[d+32]; p[d]=x0*c-x1*si; p[d+32]=x0*si+x1*c;
}
__global__ void ln_rope_ki_k(float* __restrict__ ki, const float* __restrict__ w, const float* __restrict__ b,
                             const float* __restrict__ cs, const float* __restrict__ sn){
    int s = blockIdx.x, tid = threadIdx.x;
    __shared__ float red[128]; __shared__ float buf[128];
    float v = ki[(long)s*128+tid];
    red[tid]=v; __syncthreads();
    for (int o=64;o>0;o>>=1){ if(tid<o) red[tid]+=red[tid+o]; __syncthreads(); }
    float mean = red[0]/128.f; __syncthreads();
    float d = v-mean; red[tid]=d*d; __syncthreads();
    for (int o=64;o>0;o>>=1){ if(tid<o) red[tid]+=red[tid+o]; __syncthreads(); }
    float nv = d*rsqrtf(red[0]/128.f + 1e-5f)*w[tid] + b[tid];
    buf[tid]=nv; __syncthreads();
    float out;
    if (tid<32){ float c=cs[s*32+tid], si=sn[s*32+tid]; out = buf[tid]*c - buf[tid+32]*si; }
    else if (tid<64){ int i=tid-32; float c=cs[s*32+i], si=sn[s*32+i]; out = buf[i]*si + buf[i+32]*c; }
    else out = nv;
    ki[(long)s*128+tid] = out;
}
// ---------------- indexer (fp32 SIMT, baseline-identical) ----------------
__global__ __launch_bounds__(256) void indexer_k(
    const float* __restrict__ qi, const float* __restrict__ ki,
    const float* __restrict__ wts, float* __restrict__ out){
    int t0 = blockIdx.x*64, s0 = blockIdx.y*128;
    if (t0 > s0+127) return;
    __shared__ float Bs[128][64]; __shared__ float As[16][128]; __shared__ float Ws[128][16];
    int tx = threadIdx.x, ty = threadIdx.y, tid = ty*16+tx;
    {
        int t = tid>>2, kb = (tid&3)*32;
        const float* kp = ki + (long)(t0+t)*128 + kb;
        #pragma unroll
        for (int c=0; c<32; c+=4){
            float4 v = *(const float4*)(kp+c);
            Bs[kb+c][t]=v.x; Bs[kb+c+1][t]=v.y; Bs[kb+c+2][t]=v.z; Bs[kb+c+3][t]=v.w;
        }
    }
    const float scl = 0.08838834764831845f;
    float fin[8][4] = {};
    int arow = tid>>1, acol = (tid&1)*8;
    for (int hg=0; hg<2; hg++){
        __syncthreads();
        for (int i=tid; i<2048; i+=256)
            Ws[i>>4][i&15] = wts[(long)(s0+(i>>4))*32 + hg*16 + (i&15)];
        __syncthreads();
        for (int hh=0; hh<16; hh++){
            int h = hg*16+hh;
            float acc[8][4] = {};
            #pragma unroll
            for (int kc=0; kc<8; kc++){
                const float* qp = qi + (long)(s0+arow)*4096 + h*128 + kc*16 + acol;
                float4 v0 = *(const float4*)(qp), v1 = *(const float4*)(qp+4);
                __syncthreads();
                As[acol+0][arow]=v0.x; As[acol+1][arow]=v0.y; As[acol+2][arow]=v0.z; As[acol+3][arow]=v0.w;
                As[acol+4][arow]=v1.x; As[acol+5][arow]=v1.y; As[acol+6][arow]=v1.z; As[acol+7][arow]=v1.w;
                __syncthreads();
                #pragma unroll
                for (int k=0; k<16; k++){
                    float4 a0 = *(const float4*)(&As[k][ty*8]);
                    float4 a1 = *(const float4*)(&As[k][ty*8+4]);
                    float4 b4 = *(const float4*)(&Bs[kc*16+k][tx*4]);
                    float a[8]={a0.x,a0.y,a0.z,a0.w,a1.x,a1.y,a1.z,a1.w};
                    float b[4]={b4.x,b4.y,b4.z,b4.w};
                    #pragma unroll
                    for (int i=0;i<8;i++)
                        #pragma unroll
                        for (int j=0;j<4;j++) acc[i][j]+=a[i]*b[j];
                }
            }
            #pragma unroll
            for (int i=0;i<8;i++){
                float wv = Ws[ty*8+i][hh];
                #pragma unroll
                for (int j=0;j<4;j++) fin[i][j]+=fmaxf(acc[i][j]*scl,0.f)*wv;
            }
        }
    }
    #pragma unroll
    for (int i=0;i<8;i++){
        float4 o = make_float4(fin[i][0],fin[i][1],fin[i][2],fin[i][3]);
        *(float4*)(out + (long)(s0+ty*8+i)*SQ + t0 + tx*4) = o;
    }
}
// ---------------- top-512 -> combined mask ----------------
__global__ __launch_bounds__(1024) void topk_mask_k(const float* __restrict__ iscore, float* __restrict__ comb){
    int s = blockIdx.x, tid = threadIdx.x;
    __shared__ float sv[2048]; __shared__ float xo[2048];
    __shared__ unsigned char sel[2048]; __shared__ int s_cnt;
    for (int t=tid; t<2048; t+=1024){
        float v = (t<=s) ? iscore[(long)s*SQ+t] : NEG_INF;
        xo[t]=v; sv[t]=v; sel[t]=0;
    }
    if (tid==0) s_cnt=0;
    __syncthreads();
    if (s <= TOPK-1){
        for (int t=tid; t<2048; t+=1024) comb[(long)s*SQ+t] = (t<=s)?0.f:NEG_INF;
        return;
    }
    for (int k=2;k<=2048;k<<=1)
        for (int j=k>>1;j>0;j>>=1){
            for (int t=tid;t<2048;t+=1024){
                int ixj = t^j;
                if (ixj>t){
                    float a=sv[t], b=sv[ixj];
                    bool asc = ((t&k)==0);
                    if (asc ? (a>b):(a<b)){ sv[t]=b; sv[ixj]=a; }
                }
            }
            __syncthreads();
        }
    float T = sv[2048-TOPK];
    int local=0;
    for (int t=tid;t<=s;t+=1024) if (xo[t]>T){ sel[t]=1; local++; }
    atomicAdd(&s_cnt, local);
    __syncthreads();
    if (tid==0){
        int quota = TOPK - s_cnt;
        for (int t=0; t<=s && quota>0; t++) if (!sel[t] && xo[t]==T){ sel[t]=1; quota--; }
    }
    __syncthreads();
    for (int t=tid;t<2048;t+=1024) comb[(long)s*SQ+t] = sel[t]?0.f:NEG_INF;
}
// ---------------- masked softmax ----------------
__global__ void softmax_k(float* __restrict__ scores, const float* __restrict__ comb){
    int s = blockIdx.x, h = blockIdx.y, tid = threadIdx.x;
    float* row = scores + ((long)h*SQ+s)*SQ;
    const float* cm = comb + (long)s*SQ;
    __shared__ float red[256];
    float m = NEG_INF;
    for (int t=tid;t<SQ;t+=256) if (cm[t]==0.f) m = fmaxf(m, row[t]);
    red[tid]=m; __syncthreads();
    for (int o=128;o>0;o>>=1){ if(tid<o) red[tid]=fmaxf(red[tid],red[tid+o]); __syncthreads(); }
    m = red[0]; __syncthreads();
    float sum=0.f;
    for (int t=tid;t<SQ;t+=256){
        float e = (cm[t]==0.f)?expf(row[t]-m):0.f;
        row[t]=e; sum+=e;
    }
    red[tid]=sum; __syncthreads();
    for (int o=128;o>0;o>>=1){ if(tid<o) red[tid]+=red[tid+o]; __syncthreads(); }
    float inv = 1.f/red[0];
    for (int t=tid;t<SQ;t+=256) row[t]*=inv;
}
// ---------------- PV GEMM (fp32 SIMT) ----------------
__global__ __launch_bounds__(256) void pv_gemm_k(
    const float* __restrict__ probs, const float* __restrict__ kvp, float* __restrict__ out){
    int h = blockIdx.z;
    const float* A = probs + (long)h*SQ*SQ;
    const float* B = kvp + h*256 + 128;
    float* C = out + h*128;
    int m0 = blockIdx.y*128, Kmax = m0+128;
    __shared__ float As[2][16][128]; __shared__ float Bs[2][16][128];
    int tx = threadIdx.x, ty = threadIdx.y, tid = ty*16+tx;
    int arow = tid>>1, acol = (tid&1)*8;
    int brow = tid>>4, bcol = (tid&15)*8;
    const float* Ap = A + (long)(m0+arow)*SQ + acol;
    const float* Bp = B + (long)brow*4096 + bcol;
    float4 ra0=*(const float4*)(Ap), ra1=*(const float4*)(Ap+4);
    float4 rb0=*(const float4*)(Bp), rb1=*(const float4*)(Bp+4);
    As[0][acol+0][arow]=ra0.x; As[0][acol+1][arow]=ra0.y; As[0][acol+2][arow]=ra0.z; As[0][acol+3][arow]=ra0.w;
    As[0][acol+4][arow]=ra1.x; As[0][acol+5][arow]=ra1.y; As[0][acol+6][arow]=ra1.z; As[0][acol+7][arow]=ra1.w;
    *(float4*)(&Bs[0][brow][bcol])=rb0; *(float4*)(&Bs[0][brow][bcol+4])=rb1;
    __syncthreads();
    float acc[8][8] = {};
    int nk = Kmax>>4;
    for (int kt=0; kt<nk; kt++){
        int cur = kt&1;
        if (kt+1<nk){
            const float* Ap2 = Ap + (kt+1)*16;
            const float* Bp2 = Bp + (long)(kt+1)*16*4096;
            ra0=*(const float4*)(Ap2); ra1=*(const float4*)(Ap2+4);
            rb0=*(const float4*)(Bp2); rb1=*(const float4*)(Bp2+4);
        }
        #pragma unroll
        for (int k=0;k<16;k++){
            float4 a0=*(const float4*)(&As[cur][k][ty*8]);
            float4 a1=*(const float4*)(&As[cur][k][ty*8+4]);
            float4 b0=*(const float4*)(&Bs[cur][k][tx*8]);
            float4 b1=*(const float4*)(&Bs[cur][k][tx*8+4]);
            float a[8]={a0.x,a0.y,a0.z,a0.w,a1.x,a1.y,a1.z,a1.w};
            float b[8]={b0.x,b0.y,b0.z,b0.w,b1.x,b1.y,b1.z,b1.w};
            #pragma unroll
            for (int i=0;i<8;i++)
                #pragma unroll
                for (int j=0;j<8;j++) acc[i][j]+=a[i]*b[j];
        }
        if (kt+1<nk){
            int nx = cur^1;
            As[nx][acol+0][arow]=ra0.x; As[nx][acol+1][arow]=ra0.y; As[nx][acol+2][arow]=ra0.z; As[nx][acol+3][arow]=ra0.w;
            As[nx][acol+4][arow]=ra1.x; As[nx][acol+5][arow]=ra1.y; As[nx][acol+6][arow]=ra1.z; As[nx][acol+7][arow]=ra1.w;
            *(float4*)(&Bs[nx][brow][bcol])=rb0; *(float4*)(&Bs[nx][brow][bcol+4])=rb1;
        }
        __syncthreads();
    }
    #pragma unroll
    for (int i=0;i<8;i++){
        int m = m0+ty*8+i;
        *(float4*)(C+(long)m*2048+tx*8)   = make_float4(acc[i][0],acc[i][1],acc[i][2],acc[i][3]);
        *(float4*)(C+(long)m*2048+tx*8+4) = make_float4(acc[i][4],acc[i][5],acc[i][6],acc[i][7]);
    }
}

// ================= host =================
static void cvt(const float* in, bf16* hi, bf16* lo, int n){
    cvt_hilo_k<<<(n+255)/256, 256>>>(in, hi, lo, n);
}
#define GSYM(p, s) cudaGetSymbolAddress((void**)&p, s)

extern "C" void kernel_launch(void* const* d_in, const int* in_sizes, int n_in,
                              void* d_out, int out_size)
{
    if (n_in < 16) return;
    const float *hidden,*wq_a,*q_norm_w,*wq_b,*wkv_a,*kv_norm_w,*wkv_b,*wo;
    const float *idx_wq_b,*idx_wk,*idx_kn_w,*idx_kn_b,*idx_wproj,*fcos,*fsin;
    if (in_sizes[1] == 1536*2048){
        hidden=(const float*)d_in[0];  wq_a=(const float*)d_in[1];
        q_norm_w=(const float*)d_in[2]; wq_b=(const float*)d_in[3];
        wkv_a=(const float*)d_in[4];   kv_norm_w=(const float*)d_in[5];
        wkv_b=(const float*)d_in[6];   wo=(const float*)d_in[7];
        idx_wq_b=(const float*)d_in[8]; idx_wk=(const float*)d_in[9];
        idx_kn_w=(const float*)d_in[10]; idx_kn_b=(const float*)d_in[11];
        idx_wproj=(const float*)d_in[12]; fcos=(const float*)d_in[13]; fsin=(const float*)d_in[14];
    } else {
        hidden=(const float*)d_in[0]; fcos=(const float*)d_in[1]; fsin=(const float*)d_in[2];
        wq_a=(const float*)d_in[4];   q_norm_w=(const float*)d_in[5];
        wq_b=(const float*)d_in[6];   wkv_a=(const float*)d_in[7];
        kv_norm_w=(const float*)d_in[8]; wkv_b=(const float*)d_in[9];
        wo=(const float*)d_in[10];    idx_wq_b=(const float*)d_in[11];
        idx_wk=(const float*)d_in[12]; idx_kn_w=(const float*)d_in[13];
        idx_kn_b=(const float*)d_in[14]; idx_wproj=(const float*)d_in[15];
    }

    float *qr,*q,*kvall,*kv,*kvp,*k,*qi,*ki,*wts,*iscore,*comb,*scores,*attnout;
    GSYM(qr,g_qr); GSYM(q,g_q); GSYM(kvall,g_kvall); GSYM(kv,g_kv); GSYM(kvp,g_kvp); GSYM(k,g_k);
    GSYM(qi,g_qi); GSYM(ki,g_ki); GSYM(wts,g_wts); GSYM(iscore,g_iscore);
    GSYM(comb,g_comb); GSYM(scores,g_scores); GSYM(attnout,g_attnout);
    bf16 *h_hi,*h_lo,*wqb_hi,*wqb_lo,*wkva_hi,*wkva_lo,*wkvb_hi,*wkvb_lo,*wo_hi,*wo_lo;
    bf16 *qrn_hi,*qrn_lo,*kvn_hi,*kvn_lo,*qh_hi,*qh_lo,*kh_hi,*kh_lo,*at_hi,*at_lo;
    GSYM(h_hi,g_h_hi); GSYM(h_lo,g_h_lo);
    GSYM(wqb_hi,g_wqb_hi); GSYM(wqb_lo,g_wqb_lo); GSYM(wkva_hi,g_wkva_hi); GSYM(wkva_lo,g_wkva_lo);
    GSYM(wkvb_hi,g_wkvb_hi); GSYM(wkvb_lo,g_wkvb_lo); GSYM(wo_hi,g_wo_hi); GSYM(wo_lo,g_wo_lo);
    GSYM(qrn_hi,g_qrn_hi); GSYM(qrn_lo,g_qrn_lo); GSYM(kvn_hi,g_kvn_hi); GSYM(kvn_lo,g_kvn_lo);
    GSYM(qh_hi,g_qh_hi); GSYM(qh_lo,g_qh_lo); GSYM(kh_hi,g_kh_hi); GSYM(kh_lo,g_kh_lo);
    GSYM(at_hi,g_at_hi); GSYM(at_lo,g_at_lo);
    float* outp = (float*)d_out;

    cudaFuncSetAttribute(gemm_mma_nt, cudaFuncAttributeMaxDynamicSharedMemorySize, MMA_SMEM);
    dim3 blk(16,16);
    const float inv_sqrt192 = 0.07216878364870323f;
    const float inv_sqrt32  = 0.17677669529663687f;

    // ---- indexer-critical chain: EXACT fp32 baseline path ----
    gemm_nt_k<<<dim3(12,16,1),blk>>>(hidden,0,DMM, wq_a,0,DMM, qr,0,QRR, SQ,QRR,DMM,1.f,0);
    rmsnorm_k<<<SQ,256>>>(qr,QRR, qr,QRR, q_norm_w,QRR);
    gemm_nt_k<<<dim3(32,16,1),blk>>>(qr,0,QRR, idx_wq_b,0,QRR, qi,0,4096, SQ,4096,QRR,1.f,0);
    gemm_nt_k<<<dim3(1,16,1),blk>>>(hidden,0,DMM, idx_wk,0,DMM, ki,0,128, SQ,128,DMM,1.f,0);
    gemm_nt_k<<<dim3(1,16,1),blk>>>(hidden,0,DMM, idx_wproj,0,DMM, wts,0,32, SQ,32,DMM,inv_sqrt32,0);
    rope_qi_k<<<SQ,1024>>>(qi,fcos,fsin);
    ln_rope_ki_k<<<SQ,128>>>(ki,idx_kn_w,idx_kn_b,fcos,fsin);
    indexer_k<<<dim3(SQ/64,SQ/128),blk>>>(qi,ki,wts,iscore);
    topk_mask_k<<<SQ,1024>>>(iscore,comb);

    // ---- smooth path: bf16x3 mma ----
    cvt(hidden,h_hi,h_lo,2048*2048);
    cvt(wkv_a,wkva_hi,wkva_lo,576*2048);
    cvt(wq_b,wqb_hi,wqb_lo,3072*1536);
    cvt(wkv_b,wkvb_hi,wkvb_lo,4096*512);
    cvt(wo,wo_hi,wo_lo,2048*2048);
    cvt(qr,qrn_hi,qrn_lo,2048*1536);    // qr holds normed qr

    gemm_mma_nt<<<dim3(5,16,1),256,MMA_SMEM>>>(h_hi,h_lo,0,2048, wkva_hi,wkva_lo,0,2048, kvall,0,576, 576,2048,1.f,0);
    rmsnorm_k<<<SQ,256>>>(kvall,576, kv,KRR, kv_norm_w,KRR);
    cvt(kv,kvn_hi,kvn_lo,2048*512);
    gemm_mma_nt<<<dim3(32,16,1),256,MMA_SMEM>>>(kvn_hi,kvn_lo,0,512, wkvb_hi,wkvb_lo,0,512, kvp,0,4096, 4096,512,1.f,0);
    gemm_mma_nt<<<dim3(24,16,1),256,MMA_SMEM>>>(qrn_hi,qrn_lo,0,1536, wqb_hi,wqb_lo,0,1536, q,0,3072, 3072,1536,1.f,0);
    rope_q_k<<<SQ,512>>>(q,fcos,fsin);
    build_k_k<<<dim3(SQ,NH),128>>>(kvp,kvall,k,fcos,fsin);
    cvt(q,qh_hi,qh_lo,2048*3072);
    cvt(k,kh_hi,kh_lo,2048*3072);
    gemm_mma_nt<<<dim3(16,16,16),256,MMA_SMEM>>>(qh_hi,qh_lo,192,3072, kh_hi,kh_lo,192,3072,
                                                 scores,(long)SQ*SQ,SQ, SQ,192,inv_sqrt192,1);
    softmax_k<<<dim3(SQ,NH),256>>>(scores,comb);
    pv_gemm_k<<<dim3(1,SQ/128,NH),blk>>>(scores,kvp,attnout);
    cvt(attnout,at_hi,at_lo,2048*2048);
    gemm_mma_nt<<<dim3(16,16,1),256,MMA_SMEM>>>(at_hi,at_lo,0,2048, wo_hi,wo_lo,0,2048, outp,0,2048, 2048,2048,1.f,0);
}

// round 7
// speedup vs baseline: 1.4965x; 1.1720x over previous
#include <cuda_runtime.h>
#include <cuda_bf16.h>
#include <math.h>
#include <stdint.h>

#define SQ 2048
#define NH 16
#define QRR 1536
#define KRR 512
#define TOPK 512
#define DMM 2048
#define NEG_INF (__int_as_float(0xff800000))
typedef __nv_bfloat16 bf16;

// ---------------- fp32 scratch ----------------
__device__ float g_qr[SQ*QRR];
__device__ float g_q[SQ*NH*192];
__device__ float g_kvall[SQ*576];
__device__ float g_kv[SQ*KRR];
__device__ float g_kvp[SQ*NH*256];
__device__ float g_k[SQ*NH*192];
__device__ float g_qi[SQ*32*128];
__device__ float g_ki[SQ*128];
__device__ float g_wts[SQ*32];
__device__ float g_iscore[SQ*SQ];
__device__ float g_comb[SQ*SQ];
__device__ float g_scores[67108864];
__device__ float g_attnout[SQ*DMM];
// ---------------- bf16 hi/lo scratch (smooth path only) ----------------
__device__ bf16 g_h_hi[2048*2048],  g_h_lo[2048*2048];
__device__ bf16 g_wqb_hi[3072*1536],g_wqb_lo[3072*1536];
__device__ bf16 g_wkva_hi[576*2048],g_wkva_lo[576*2048];
__device__ bf16 g_wkvb_hi[4096*512],g_wkvb_lo[4096*512];
__device__ bf16 g_wo_hi[2048*2048], g_wo_lo[2048*2048];
__device__ bf16 g_qrn_hi[2048*1536],g_qrn_lo[2048*1536];
__device__ bf16 g_kvn_hi[2048*512], g_kvn_lo[2048*512];
__device__ bf16 g_qh_hi[2048*3072], g_qh_lo[2048*3072];
__device__ bf16 g_kh_hi[2048*3072], g_kh_lo[2048*3072];
__device__ bf16 g_at_hi[2048*2048], g_at_lo[2048*2048];
__device__ bf16 g_p_hi[67108864],   g_p_lo[67108864];    // probs [h][s][t]
__device__ bf16 g_vT_hi[16*128*2048], g_vT_lo[16*128*2048]; // v^T [h][n][k]

// ================= mma.sync helpers =================
__device__ __forceinline__ uint32_t smem_u32(const void* p){
    uint32_t a; asm("{ .reg .u64 t; cvta.to.shared.u64 t, %1; cvt.u32.u64 %0, t; }":"=r"(a):"l"(p)); return a;
}
#define LDSM4(R, ADDR) asm volatile( \
    "ldmatrix.sync.aligned.m8n8.x4.shared.b16 {%0,%1,%2,%3}, [%4];" \
    : "=r"((R)[0]),"=r"((R)[1]),"=r"((R)[2]),"=r"((R)[3]) : "r"(ADDR))
#define MMA16816(D, A, B) asm volatile( \
    "mma.sync.aligned.m16n8k16.row.col.f32.bf16.bf16.f32 " \
    "{%0,%1,%2,%3}, {%4,%5,%6,%7}, {%8,%9}, {%0,%1,%2,%3};" \
    : "+f"((D)[0]),"+f"((D)[1]),"+f"((D)[2]),"+f"((D)[3]) \
    : "r"((A)[0]),"r"((A)[1]),"r"((A)[2]),"r"((A)[3]), "r"((B)[0]),"r"((B)[1]))

// ======= bf16x3 NT GEMM via mma.sync (smooth path) =======
// causal: 0=dense, 1=skip tiles above diagonal, 2=K capped at m0+128 (PV)
#define LSTR 72
#define MMA_SMEM (4*128*LSTR*2)
__global__ __launch_bounds__(256) void gemm_mma_nt(
    const bf16* __restrict__ Ah, const bf16* __restrict__ Al, long sa, int lda,
    const bf16* __restrict__ Bh, const bf16* __restrict__ Bl, long sb, int ldb,
    float* __restrict__ C, long sc, int ldc, int N, int K, float alpha, int causal)
{
    int n0 = blockIdx.x*128, m0 = blockIdx.y*128;
    if (causal == 1 && n0 > m0+127) return;
    int Keff = K;
    if (causal == 2 && m0+128 < Keff) Keff = m0+128;
    Ah += (long)blockIdx.z*sa; Al += (long)blockIdx.z*sa;
    Bh += (long)blockIdx.z*sb; Bl += (long)blockIdx.z*sb;
    C  += (long)blockIdx.z*sc;

    extern __shared__ bf16 sm[];
    bf16 *sAh = sm, *sAl = sm + 128*LSTR, *sBh = sm + 2*128*LSTR, *sBl = sm + 3*128*LSTR;
    int tid = threadIdx.x, lane = tid & 31, wid = tid >> 5;
    int wm = (wid >> 1) * 32, wn = (wid & 1) * 64;
    float acc[2][8][4] = {};

    for (int kc = 0; kc < Keff; kc += 64){
        __syncthreads();
        #pragma unroll
        for (int it = 0; it < 4; it++){
            int c = tid + it*256, row = c >> 3, cb = (c & 7) * 8;
            long ga = (long)(m0+row)*lda + kc + cb;
            *(int4*)&sAh[row*LSTR + cb] = *(const int4*)(Ah + ga);
            *(int4*)&sAl[row*LSTR + cb] = *(const int4*)(Al + ga);
            int4 vh = make_int4(0,0,0,0), vl = vh;
            if (n0 + row < N){
                long gb = (long)(n0+row)*ldb + kc + cb;
                vh = *(const int4*)(Bh + gb); vl = *(const int4*)(Bl + gb);
            }
            *(int4*)&sBh[row*LSTR + cb] = vh;
            *(int4*)&sBl[row*LSTR + cb] = vl;
        }
        __syncthreads();

        int r = lane & 15, ko = (lane >> 4) * 8;
        #pragma unroll
        for (int ks = 0; ks < 4; ks++){
            uint32_t ah[2][4], al[2][4], bh[8][2], bl[8][2];
            #pragma unroll
            for (int mi = 0; mi < 2; mi++){
                uint32_t ad = smem_u32(&sAh[(wm + mi*16 + r)*LSTR + ks*16 + ko]);
                LDSM4(ah[mi], ad);
                ad = smem_u32(&sAl[(wm + mi*16 + r)*LSTR + ks*16 + ko]);
                LDSM4(al[mi], ad);
            }
            #pragma unroll
            for (int np = 0; np < 4; np++){
                uint32_t t4[4];
                uint32_t bd = smem_u32(&sBh[(wn + np*16 + r)*LSTR + ks*16 + ko]);
                LDSM4(t4, bd);
                bh[2*np][0]=t4[0]; bh[2*np][1]=t4[2]; bh[2*np+1][0]=t4[1]; bh[2*np+1][1]=t4[3];
                bd = smem_u32(&sBl[(wn + np*16 + r)*LSTR + ks*16 + ko]);
                LDSM4(t4, bd);
                bl[2*np][0]=t4[0]; bl[2*np][1]=t4[2]; bl[2*np+1][0]=t4[1]; bl[2*np+1][1]=t4[3];
            }
            #pragma unroll
            for (int mi = 0; mi < 2; mi++)
                #pragma unroll
                for (int ni = 0; ni < 8; ni++){
                    MMA16816(acc[mi][ni], ah[mi], bh[ni]);
                    MMA16816(acc[mi][ni], ah[mi], bl[ni]);
                    MMA16816(acc[mi][ni], al[mi], bh[ni]);
                }
        }
    }
    #pragma unroll
    for (int mi = 0; mi < 2; mi++){
        int mrow = m0 + wm + mi*16 + (lane >> 2);
        #pragma unroll
        for (int ni = 0; ni < 8; ni++){
            int n = n0 + wn + ni*8 + (lane & 3)*2;
            if (n < N){
                *(float2*)(C + (long)mrow*ldc + n)     = make_float2(alpha*acc[mi][ni][0], alpha*acc[mi][ni][1]);
                *(float2*)(C + (long)(mrow+8)*ldc + n) = make_float2(alpha*acc[mi][ni][2], alpha*acc[mi][ni][3]);
            }
        }
    }
}

// ======= fp32 SIMT NT GEMM (bit-identical baseline) =======
__global__ __launch_bounds__(256) void gemm_nt_k(
    const float* __restrict__ A, long sa, int lda,
    const float* __restrict__ B, long sb, int ldb,
    float* __restrict__ C, long sc, int ldc,
    int M, int N, int K, float alpha, int causal)
{
    A += (long)blockIdx.z*sa; B += (long)blockIdx.z*sb; C += (long)blockIdx.z*sc;
    int n0 = blockIdx.x*128, m0 = blockIdx.y*128;
    if (causal && n0 > m0+127) return;
    __shared__ float As[2][16][128];
    __shared__ float Bs[2][16][128];
    int tx = threadIdx.x, ty = threadIdx.y, tid = ty*16+tx;
    int lrow = tid>>1, lcol = (tid&1)*8;
    const float* Ap = A + (long)(m0+lrow)*lda + lcol;
    const float* Bp = B + (long)(n0+lrow)*ldb + lcol;
    bool aval = (m0+lrow) < M, bval = (n0+lrow) < N;
    float4 ra0, ra1, rb0, rb1;
    const float4 z4 = make_float4(0.f,0.f,0.f,0.f);
    ra0 = aval ? *(const float4*)(Ap)   : z4;
    ra1 = aval ? *(const float4*)(Ap+4) : z4;
    rb0 = bval ? *(const float4*)(Bp)   : z4;
    rb1 = bval ? *(const float4*)(Bp+4) : z4;
    As[0][lcol+0][lrow]=ra0.x; As[0][lcol+1][lrow]=ra0.y; As[0][lcol+2][lrow]=ra0.z; As[0][lcol+3][lrow]=ra0.w;
    As[0][lcol+4][lrow]=ra1.x; As[0][lcol+5][lrow]=ra1.y; As[0][lcol+6][lrow]=ra1.z; As[0][lcol+7][lrow]=ra1.w;
    Bs[0][lcol+0][lrow]=rb0.x; Bs[0][lcol+1][lrow]=rb0.y; Bs[0][lcol+2][lrow]=rb0.z; Bs[0][lcol+3][lrow]=rb0.w;
    Bs[0][lcol+4][lrow]=rb1.x; Bs[0][lcol+5][lrow]=rb1.y; Bs[0][lcol+6][lrow]=rb1.z; Bs[0][lcol+7][lrow]=rb1.w;
    __syncthreads();
    float acc[8][8] = {};
    int nk = K>>4;
    for (int kt=0; kt<nk; kt++){
        int cur = kt&1;
        if (kt+1<nk){
            const float* Ap2 = Ap + (kt+1)*16;
            const float* Bp2 = Bp + (kt+1)*16;
            ra0 = aval ? *(const float4*)(Ap2)   : z4;
            ra1 = aval ? *(const float4*)(Ap2+4) : z4;
            rb0 = bval ? *(const float4*)(Bp2)   : z4;
            rb1 = bval ? *(const float4*)(Bp2+4) : z4;
        }
        #pragma unroll
        for (int k=0;k<16;k++){
            float4 a0=*(const float4*)(&As[cur][k][ty*8]);
            float4 a1=*(const float4*)(&As[cur][k][ty*8+4]);
            float4 b0=*(const float4*)(&Bs[cur][k][tx*8]);
            float4 b1=*(const float4*)(&Bs[cur][k][tx*8+4]);
            float a[8]={a0.x,a0.y,a0.z,a0.w,a1.x,a1.y,a1.z,a1.w};
            float b[8]={b0.x,b0.y,b0.z,b0.w,b1.x,b1.y,b1.z,b1.w};
            #pragma unroll
            for (int i=0;i<8;i++)
                #pragma unroll
                for (int j=0;j<8;j++) acc[i][j]+=a[i]*b[j];
        }
        if (kt+1<nk){
            int nx = cur^1;
            As[nx][lcol+0][lrow]=ra0.x; As[nx][lcol+1][lrow]=ra0.y; As[nx][lcol+2][lrow]=ra0.z; As[nx][lcol+3][lrow]=ra0.w;
            As[nx][lcol+4][lrow]=ra1.x; As[nx][lcol+5][lrow]=ra1.y; As[nx][lcol+6][lrow]=ra1.z; As[nx][lcol+7][lrow]=ra1.w;
            Bs[nx][lcol+0][lrow]=rb0.x; Bs[nx][lcol+1][lrow]=rb0.y; Bs[nx][lcol+2][lrow]=rb0.z; Bs[nx][lcol+3][lrow]=rb0.w;
            Bs[nx][lcol+4][lrow]=rb1.x; Bs[nx][lcol+5][lrow]=rb1.y; Bs[nx][lcol+6][lrow]=rb1.z; Bs[nx][lcol+7][lrow]=rb1.w;
        }
        __syncthreads();
    }
    #pragma unroll
    for (int i=0;i<8;i++){
        int m = m0+ty*8+i;
        if (m >= M) continue;
        int n = n0+tx*8;
        if (n < N){
            *(float4*)(C+(long)m*ldc+n)   = make_float4(acc[i][0]*alpha,acc[i][1]*alpha,acc[i][2]*alpha,acc[i][3]*alpha);
            *(float4*)(C+(long)m*ldc+n+4) = make_float4(acc[i][4]*alpha,acc[i][5]*alpha,acc[i][6]*alpha,acc[i][7]*alpha);
        }
    }
}

// ======= fused skinny GEMM: ki (N=128) + wts (N=32), bit-identical =======
// Each thread owns one output column n (0..127 -> ki, 128..159 -> wts) and
// accumulates k-ascending in a single fp32 accumulator per output (same FMA
// chain as gemm_nt_k).
#define SKC 64
__global__ __launch_bounds__(160) void skinny_k(
    const float* __restrict__ A,   // hidden [2048 x 2048]
    const float* __restrict__ B1,  // idx_wk [128 x 2048]
    const float* __restrict__ B2,  // idx_wproj [32 x 2048]
    float* __restrict__ C1, float* __restrict__ C2, float alpha2)
{
    __shared__ float sA[16][SKC];
    __shared__ float sB[160][SKC+1];
    int tid = threadIdx.x;                 // 0..159
    int m0 = blockIdx.x * 16;
    const float* Brow = (tid < 128) ? (B1 + (long)tid*2048) : (B2 + (long)(tid-128)*2048);
    float acc[16] = {};
    for (int kc = 0; kc < 2048; kc += SKC){
        __syncthreads();
        for (int i = tid; i < 16*SKC; i += 160){
            int r = i / SKC, c = i - r*SKC;
            sA[r][c] = A[(long)(m0+r)*2048 + kc + c];
        }
        #pragma unroll
        for (int c = 0; c < SKC; c += 4){
            float4 v = *(const float4*)(Brow + kc + c);
            sB[tid][c]=v.x; sB[tid][c+1]=v.y; sB[tid][c+2]=v.z; sB[tid][c+3]=v.w;
        }
        __syncthreads();
        #pragma unroll
        for (int k = 0; k < SKC; k++){
            float bv = sB[tid][k];
            #pragma unroll
            for (int m = 0; m < 16; m++) acc[m] += sA[m][k]*bv;
        }
    }
    if (tid < 128){
        for (int m = 0; m < 16; m++) C1[(long)(m0+m)*128 + tid] = acc[m];
    } else {
        int n = tid - 128;
        for (int m = 0; m < 16; m++) C2[(long)(m0+m)*32 + n] = acc[m]*alpha2;
    }
}

// ---------------- cvt / norms / ropes ----------------
__global__ void cvt_hilo_k(const float* __restrict__ in, bf16* __restrict__ hi, bf16* __restrict__ lo, int n){
    int i = blockIdx.x*256 + threadIdx.x;
    if (i < n){
        float x = in[i]; bf16 h = __float2bfloat16(x);
        hi[i] = h; lo[i] = __float2bfloat16(x - __bfloat162float(h));
    }
}
__global__ void rmsnorm_k(const float* __restrict__ in, int ldi,
                          float* __restrict__ out, int ldo,
                          const float* __restrict__ w, int D){
    int s = blockIdx.x, tid = threadIdx.x;
    __shared__ float red[256];
    const float* ip = in + (long)s*ldi;
    float ss = 0.f;
    for (int d=tid; d<D; d+=256){ float v = ip[d]; ss += v*v; }
    red[tid]=ss; __syncthreads();
    for (int o=128;o>0;o>>=1){ if(tid<o) red[tid]+=red[tid+o]; __syncthreads(); }
    float scale = rsqrtf(red[0]/(float)D + 1e-6f);
    float* op = out + (long)s*ldo;
    for (int d=tid; d<D; d+=256) op[d] = ip[d]*scale*w[d];
}
__global__ void rope_q_k(float* __restrict__ q, const float* __restrict__ cs, const float* __restrict__ sn){
    int s = blockIdx.x, tid = threadIdx.x, h = tid>>5, i = tid&31;
    float c = cs[s*32+i], si = sn[s*32+i];
    float* p = q + (long)s*3072 + h*192 + 128 + 2*i;
    float x0=p[0], x1=p[1]; p[0]=x0*c-x1*si; p[1]=x0*si+x1*c;
}
__global__ void build_k_k(const float* __restrict__ kvp, const float* __restrict__ kvall,
                          float* __restrict__ kk, const float* __restrict__ cs, const float* __restrict__ sn){
    int s = blockIdx.x, h = blockIdx.y, tid = threadIdx.x;
    float* dst = kk + ((long)s*16+h)*192;
    dst[tid] = kvp[(long)s*4096 + h*256 + tid];
    if (tid < 32){
        float c = cs[s*32+tid], si = sn[s*32+tid];
        float x0 = kvall[(long)s*576+512+2*tid], x1 = kvall[(long)s*576+513+2*tid];
        dst[128+2*tid]=x0*c-x1*si; dst[129+2*tid]=x0*si+x1*c;
    }
}
__global__ void rope_qi_k(float* __restrict__ qi, const float* __restrict__ cs, const float* __restrict__ sn){
    int s = blockIdx.x, tid = threadIdx.x, h = tid>>5, d = tid&31;
    float c = cs[s*32+d], si = sn[s*32+d];
    float* p = qi + (long)s*4096 + h*128;
    float x0=p[d], x1=p[d+32]; p[d]=x0*c-x1*si; p[d+32]=x0*si+x1*c;
}
__global__ void ln_rope_ki_k(float* __restrict__ ki, const float* __restrict__ w, const float* __restrict__ b,
                             const float* __restrict__ cs, const float* __restrict__ sn){
    int s = blockIdx.x, tid = threadIdx.x;
    __shared__ float red[128]; __shared__ float buf[128];
    float v = ki[(long)s*128+tid];
    red[tid]=v; __syncthreads();
    for (int o=64;o>0;o>>=1){ if(tid<o) red[tid]+=red[tid+o]; __syncthreads(); }
    float mean = red[0]/128.f; __syncthreads();
    float d = v-mean; red[tid]=d*d; __syncthreads();
    for (int o=64;o>0;o>>=1){ if(tid<o) red[tid]+=red[tid+o]; __syncthreads(); }
    float nv = d*rsqrtf(red[0]/128.f + 1e-5f)*w[tid] + b[tid];
    buf[tid]=nv; __syncthreads();
    float out;
    if (tid<32){ float c=cs[s*32+tid], si=sn[s*32+tid]; out = buf[tid]*c - buf[tid+32]*si; }
    else if (tid<64){ int i=tid-32; float c=cs[s*32+i], si=sn[s*32+i]; out = buf[i]*si + buf[i+32]*c; }
    else out = nv;
    ki[(long)s*128+tid] = out;
}
// ---------------- indexer (fp32 SIMT, baseline-identical) ----------------
__global__ __launch_bounds__(256) void indexer_k(
    const float* __restrict__ qi, const float* __restrict__ ki,
    const float* __restrict__ wts, float* __restrict__ out){
    int t0 = blockIdx.x*64, s0 = blockIdx.y*128;
    if (t0 > s0+127) return;
    __shared__ float Bs[128][64]; __shared__ float As[16][128]; __shared__ float Ws[128][16];
    int tx = threadIdx.x, ty = threadIdx.y, tid = ty*16+tx;
    {
        int t = tid>>2, kb = (tid&3)*32;
        const float* kp = ki + (long)(t0+t)*128 + kb;
        #pragma unroll
        for (int c=0; c<32; c+=4){
            float4 v = *(const float4*)(kp+c);
            Bs[kb+c][t]=v.x; Bs[kb+c+1][t]=v.y; Bs[kb+c+2][t]=v.z; Bs[kb+c+3][t]=v.w;
        }
    }
    const float scl = 0.08838834764831845f;
    float fin[8][4] = {};
    int arow = tid>>1, acol = (tid&1)*8;
    for (int hg=0; hg<2; hg++){
        __syncthreads();
        for (int i=tid; i<2048; i+=256)
            Ws[i>>4][i&15] = wts[(long)(s0+(i>>4))*32 + hg*16 + (i&15)];
        __syncthreads();
        for (int hh=0; hh<16; hh++){
            int h = hg*16+hh;
            float acc[8][4] = {};
            #pragma unroll
            for (int kc=0; kc<8; kc++){
                const float* qp = qi + (long)(s0+arow)*4096 + h*128 + kc*16 + acol;
                float4 v0 = *(const float4*)(qp), v1 = *(const float4*)(qp+4);
                __syncthreads();
                As[acol+0][arow]=v0.x; As[acol+1][arow]=v0.y; As[acol+2][arow]=v0.z; As[acol+3][arow]=v0.w;
                As[acol+4][arow]=v1.x; As[acol+5][arow]=v1.y; As[acol+6][arow]=v1.z; As[acol+7][arow]=v1.w;
                __syncthreads();
                #pragma unroll
                for (int k=0; k<16; k++){
                    float4 a0 = *(const float4*)(&As[k][ty*8]);
                    float4 a1 = *(const float4*)(&As[k][ty*8+4]);
                    float4 b4 = *(const float4*)(&Bs[kc*16+k][tx*4]);
                    float a[8]={a0.x,a0.y,a0.z,a0.w,a1.x,a1.y,a1.z,a1.w};
                    float b[4]={b4.x,b4.y,b4.z,b4.w};
                    #pragma unroll
                    for (int i=0;i<8;i++)
                        #pragma unroll
                        for (int j=0;j<4;j++) acc[i][j]+=a[i]*b[j];
                }
            }
            #pragma unroll
            for (int i=0;i<8;i++){
                float wv = Ws[ty*8+i][hh];
                #pragma unroll
                for (int j=0;j<4;j++) fin[i][j]+=fmaxf(acc[i][j]*scl,0.f)*wv;
            }
        }
    }
    #pragma unroll
    for (int i=0;i<8;i++){
        float4 o = make_float4(fin[i][0],fin[i][1],fin[i][2],fin[i][3]);
        *(float4*)(out + (long)(s0+ty*8+i)*SQ + t0 + tx*4) = o;
    }
}
// ---------------- top-512 -> combined mask ----------------
__global__ __launch_bounds__(1024) void topk_mask_k(const float* __restrict__ iscore, float* __restrict__ comb){
    int s = blockIdx.x, tid = threadIdx.x;
    __shared__ float sv[2048]; __shared__ float xo[2048];
    __shared__ unsigned char sel[2048]; __shared__ int s_cnt;
    for (int t=tid; t<2048; t+=1024){
        float v = (t<=s) ? iscore[(long)s*SQ+t] : NEG_INF;
        xo[t]=v; sv[t]=v; sel[t]=0;
    }
    if (tid==0) s_cnt=0;
    __syncthreads();
    if (s <= TOPK-1){
        for (int t=tid; t<2048; t+=1024) comb[(long)s*SQ+t] = (t<=s)?0.f:NEG_INF;
        return;
    }
    for (int k=2;k<=2048;k<<=1)
        for (int j=k>>1;j>0;j>>=1){
            for (int t=tid;t<2048;t+=1024){
                int ixj = t^j;
                if (ixj>t){
                    float a=sv[t], b=sv[ixj];
                    bool asc = ((t&k)==0);
                    if (asc ? (a>b):(a<b)){ sv[t]=b; sv[ixj]=a; }
                }
            }
            __syncthreads();
        }
    float T = sv[2048-TOPK];
    int local=0;
    for (int t=tid;t<=s;t+=1024) if (xo[t]>T){ sel[t]=1; local++; }
    atomicAdd(&s_cnt, local);
    __syncthreads();
    if (tid==0){
        int quota = TOPK - s_cnt;
        for (int t=0; t<=s && quota>0; t++) if (!sel[t] && xo[t]==T){ sel[t]=1; quota--; }
    }
    __syncthreads();
    for (int t=tid;t<2048;t+=1024) comb[(long)s*SQ+t] = sel[t]?0.f:NEG_INF;
}
// ---------------- masked softmax -> bf16 hi/lo probs, range-limited --------
__global__ void softmax2_k(const float* __restrict__ scores, const float* __restrict__ comb,
                           bf16* __restrict__ phi, bf16* __restrict__ plo){
    int s = blockIdx.x, h = blockIdx.y, tid = threadIdx.x;
    long ro = ((long)h*SQ+s)*SQ;
    const float* row = scores + ro;
    const float* cm = comb + (long)s*SQ;
    int lim = ((s>>7)+1)<<7;                 // round_up(s+1, 128)
    __shared__ float red[256];
    float m = NEG_INF;
    for (int t=tid;t<lim;t+=256) if (cm[t]==0.f) m = fmaxf(m, row[t]);
    red[tid]=m; __syncthreads();
    for (int o=128;o>0;o>>=1){ if(tid<o) red[tid]=fmaxf(red[tid],red[tid+o]); __syncthreads(); }
    m = red[0]; __syncthreads();
    float sum=0.f;
    for (int t=tid;t<lim;t+=256)
        if (cm[t]==0.f) sum += expf(row[t]-m);
    red[tid]=sum; __syncthreads();
    for (int o=128;o>0;o>>=1){ if(tid<o) red[tid]+=red[tid+o]; __syncthreads(); }
    float inv = 1.f/red[0];
    for (int t=tid;t<lim;t+=256){
        float p = (cm[t]==0.f) ? expf(row[t]-m)*inv : 0.f;
        bf16 hb = __float2bfloat16(p);
        phi[ro+t] = hb;
        plo[ro+t] = __float2bfloat16(p - __bfloat162float(hb));
    }
}
// ---------------- v^T build: kvp -> vT[h][n][k] bf16 hi/lo -----------------
__global__ void build_vT_k(const float* __restrict__ kvp, bf16* __restrict__ vhi, bf16* __restrict__ vlo){
    int s = blockIdx.x*256 + threadIdx.x;    // 8 blocks x 256
    int n = blockIdx.y, h = blockIdx.z;
    float v = kvp[(long)s*4096 + h*256 + 128 + n];
    long o = ((long)h*128 + n)*2048 + s;
    bf16 hb = __float2bfloat16(v);
    vhi[o] = hb; vlo[o] = __float2bfloat16(v - __bfloat162float(hb));
}

// ================= host =================
static void cvt(const float* in, bf16* hi, bf16* lo, int n){
    cvt_hilo_k<<<(n+255)/256, 256>>>(in, hi, lo, n);
}
#define GSYM(p, s) cudaGetSymbolAddress((void**)&p, s)

extern "C" void kernel_launch(void* const* d_in, const int* in_sizes, int n_in,
                              void* d_out, int out_size)
{
    if (n_in < 16) return;
    const float *hidden,*wq_a,*q_norm_w,*wq_b,*wkv_a,*kv_norm_w,*wkv_b,*wo;
    const float *idx_wq_b,*idx_wk,*idx_kn_w,*idx_kn_b,*idx_wproj,*fcos,*fsin;
    if (in_sizes[1] == 1536*2048){
        hidden=(const float*)d_in[0];  wq_a=(const float*)d_in[1];
        q_norm_w=(const float*)d_in[2]; wq_b=(const float*)d_in[3];
        wkv_a=(const float*)d_in[4];   kv_norm_w=(const float*)d_in[5];
        wkv_b=(const float*)d_in[6];   wo=(const float*)d_in[7];
        idx_wq_b=(const float*)d_in[8]; idx_wk=(const float*)d_in[9];
        idx_kn_w=(const float*)d_in[10]; idx_kn_b=(const float*)d_in[11];
        idx_wproj=(const float*)d_in[12]; fcos=(const float*)d_in[13]; fsin=(const float*)d_in[14];
    } else {
        hidden=(const float*)d_in[0]; fcos=(const float*)d_in[1]; fsin=(const float*)d_in[2];
        wq_a=(const float*)d_in[4];   q_norm_w=(const float*)d_in[5];
        wq_b=(const float*)d_in[6];   wkv_a=(const float*)d_in[7];
        kv_norm_w=(const float*)d_in[8]; wkv_b=(const float*)d_in[9];
        wo=(const float*)d_in[10];    idx_wq_b=(const float*)d_in[11];
        idx_wk=(const float*)d_in[12]; idx_kn_w=(const float*)d_in[13];
        idx_kn_b=(const float*)d_in[14]; idx_wproj=(const float*)d_in[15];
    }

    float *qr,*q,*kvall,*kv,*kvp,*k,*qi,*ki,*wts,*iscore,*comb,*scores,*attnout;
    GSYM(qr,g_qr); GSYM(q,g_q); GSYM(kvall,g_kvall); GSYM(kv,g_kv); GSYM(kvp,g_kvp); GSYM(k,g_k);
    GSYM(qi,g_qi); GSYM(ki,g_ki); GSYM(wts,g_wts); GSYM(iscore,g_iscore);
    GSYM(comb,g_comb); GSYM(scores,g_scores); GSYM(attnout,g_attnout);
    bf16 *h_hi,*h_lo,*wqb_hi,*wqb_lo,*wkva_hi,*wkva_lo,*wkvb_hi,*wkvb_lo,*wo_hi,*wo_lo;
    bf16 *qrn_hi,*qrn_lo,*kvn_hi,*kvn_lo,*qh_hi,*qh_lo,*kh_hi,*kh_lo,*at_hi,*at_lo;
    bf16 *p_hi,*p_lo,*vT_hi,*vT_lo;
    GSYM(h_hi,g_h_hi); GSYM(h_lo,g_h_lo);
    GSYM(wqb_hi,g_wqb_hi); GSYM(wqb_lo,g_wqb_lo); GSYM(wkva_hi,g_wkva_hi); GSYM(wkva_lo,g_wkva_lo);
    GSYM(wkvb_hi,g_wkvb_hi); GSYM(wkvb_lo,g_wkvb_lo); GSYM(wo_hi,g_wo_hi); GSYM(wo_lo,g_wo_lo);
    GSYM(qrn_hi,g_qrn_hi); GSYM(qrn_lo,g_qrn_lo); GSYM(kvn_hi,g_kvn_hi); GSYM(kvn_lo,g_kvn_lo);
    GSYM(qh_hi,g_qh_hi); GSYM(qh_lo,g_qh_lo); GSYM(kh_hi,g_kh_hi); GSYM(kh_lo,g_kh_lo);
    GSYM(at_hi,g_at_hi); GSYM(at_lo,g_at_lo);
    GSYM(p_hi,g_p_hi); GSYM(p_lo,g_p_lo); GSYM(vT_hi,g_vT_hi); GSYM(vT_lo,g_vT_lo);
    float* outp = (float*)d_out;

    cudaFuncSetAttribute(gemm_mma_nt, cudaFuncAttributeMaxDynamicSharedMemorySize, MMA_SMEM);
    dim3 blk(16,16);
    const float inv_sqrt192 = 0.07216878364870323f;
    const float inv_sqrt32  = 0.17677669529663687f;

    // ---- indexer-critical chain: EXACT fp32 baseline numerics ----
    gemm_nt_k<<<dim3(12,16,1),blk>>>(hidden,0,DMM, wq_a,0,DMM, qr,0,QRR, SQ,QRR,DMM,1.f,0);
    rmsnorm_k<<<SQ,256>>>(qr,QRR, qr,QRR, q_norm_w,QRR);
    gemm_nt_k<<<dim3(32,16,1),blk>>>(qr,0,QRR, idx_wq_b,0,QRR, qi,0,4096, SQ,4096,QRR,1.f,0);
    skinny_k<<<128,160>>>(hidden, idx_wk, idx_wproj, ki, wts, inv_sqrt32);
    rope_qi_k<<<SQ,1024>>>(qi,fcos,fsin);
    ln_rope_ki_k<<<SQ,128>>>(ki,idx_kn_w,idx_kn_b,fcos,fsin);
    indexer_k<<<dim3(SQ/64,SQ/128),blk>>>(qi,ki,wts,iscore);
    topk_mask_k<<<SQ,1024>>>(iscore,comb);

    // ---- smooth path: bf16x3 mma ----
    cvt(hidden,h_hi,h_lo,2048*2048);
    cvt(wkv_a,wkva_hi,wkva_lo,576*2048);
    cvt(wq_b,wqb_hi,wqb_lo,3072*1536);
    cvt(wkv_b,wkvb_hi,wkvb_lo,4096*512);
    cvt(wo,wo_hi,wo_lo,2048*2048);
    cvt(qr,qrn_hi,qrn_lo,2048*1536);    // qr holds normed qr

    gemm_mma_nt<<<dim3(5,16,1),256,MMA_SMEM>>>(h_hi,h_lo,0,2048, wkva_hi,wkva_lo,0,2048, kvall,0,576, 576,2048,1.f,0);
    rmsnorm_k<<<SQ,256>>>(kvall,576, kv,KRR, kv_norm_w,KRR);
    cvt(kv,kvn_hi,kvn_lo,2048*512);
    gemm_mma_nt<<<dim3(32,16,1),256,MMA_SMEM>>>(kvn_hi,kvn_lo,0,512, wkvb_hi,wkvb_lo,0,512, kvp,0,4096, 4096,512,1.f,0);
    gemm_mma_nt<<<dim3(24,16,1),256,MMA_SMEM>>>(qrn_hi,qrn_lo,0,1536, wqb_hi,wqb_lo,0,1536, q,0,3072, 3072,1536,1.f,0);
    rope_q_k<<<SQ,512>>>(q,fcos,fsin);
    build_k_k<<<dim3(SQ,NH),128>>>(kvp,kvall,k,fcos,fsin);
    cvt(q,qh_hi,qh_lo,2048*3072);
    cvt(k,kh_hi,kh_lo,2048*3072);
    gemm_mma_nt<<<dim3(16,16,16),256,MMA_SMEM>>>(qh_hi,qh_lo,192,3072, kh_hi,kh_lo,192,3072,
                                                 scores,(long)SQ*SQ,SQ, SQ,192,inv_sqrt192,1);
    softmax2_k<<<dim3(SQ,NH),256>>>(scores,comb,p_hi,p_lo);
    build_vT_k<<<dim3(8,128,16),256>>>(kvp, vT_hi, vT_lo);
    // PV: attn_out[:, h*128 : h*128+128] = probs_h @ vT_h^T (K capped per tile)
    gemm_mma_nt<<<dim3(1,16,16),256,MMA_SMEM>>>(p_hi,p_lo,(long)SQ*SQ,SQ, vT_hi,vT_lo,(long)128*2048,2048,
                                                attnout,128,2048, 128,2048,1.f,2);
    cvt(attnout,at_hi,at_lo,2048*2048);
    gemm_mma_nt<<<dim3(16,16,1),256,MMA_SMEM>>>(at_hi,at_lo,0,2048, wo_hi,wo_lo,0,2048, outp,0,2048, 2048,2048,1.f,0);
}